// round 1
// baseline (speedup 1.0000x reference)
#include <cuda_runtime.h>
#include <cstdint>

#define BATCH 2
#define SEQ 2048
#define DIM 1024
#define HEADS 16
#define DHEAD 64
#define BS (BATCH*SEQ)   // 4096

// ---------------- scratch (device globals; no allocations allowed) ----------
__device__ float g_q[BS*DIM];     // [b,n,h,e]
__device__ float g_k[BS*DIM];
__device__ float g_v[BS*DIM];
__device__ float g_agg[BS*DIM];   // [b,n,h,e]
__device__ float g_wq[DIM*DIM];   // packed [d][h*64+e], SCALE folded
__device__ float g_wk[DIM*DIM];
__device__ float g_wv[DIM*DIM];

// ---------------- weight packing: [h,d,e] -> [d, h*64+e] --------------------
__global__ void pack_w(const float* __restrict__ wq,
                       const float* __restrict__ wk,
                       const float* __restrict__ wv) {
    int idx = blockIdx.x * blockDim.x + threadIdx.x;
    if (idx >= DIM * DIM) return;
    int d = idx >> 10;        // /1024
    int c = idx & 1023;
    int h = c >> 6;
    int e = c & 63;
    int src = (h * DIM + d) * DHEAD + e;
    g_wq[idx] = wq[src] * 0.125f;   // SCALE = 64^-0.5
    g_wk[idx] = wk[src];
    g_wv[idx] = wv[src];
}

// ---------------- fp32 SGEMM: C[M,N] = A[M,K] * B[K,N], row-major -----------
#define BM 128
#define BN 128
#define BK 16

__global__ __launch_bounds__(256) void sgemm(const float* __restrict__ A,
                                             const float* __restrict__ B,
                                             float* __restrict__ C,
                                             int M, int N, int K) {
    __shared__ float As[BK][BM + 4];   // transposed A tile, padded
    __shared__ float Bs[BK][BN];

    const int tid = threadIdx.x;
    const int tx = tid & 15;           // 16 across N
    const int ty = tid >> 4;           // 16 across M
    const int row0 = blockIdx.y * BM;
    const int col0 = blockIdx.x * BN;

    float acc[8][8] = {};

    for (int k0 = 0; k0 < K; k0 += BK) {
#pragma unroll
        for (int r = 0; r < 2; r++) {
            int i = tid + 256 * r;
            int ar = i >> 2, ac = (i & 3) * 4;
            float4 av = *reinterpret_cast<const float4*>(
                &A[(size_t)(row0 + ar) * K + k0 + ac]);
            As[ac + 0][ar] = av.x;
            As[ac + 1][ar] = av.y;
            As[ac + 2][ar] = av.z;
            As[ac + 3][ar] = av.w;
            int br = i >> 5, bc = (i & 31) * 4;
            *reinterpret_cast<float4*>(&Bs[br][bc]) =
                *reinterpret_cast<const float4*>(
                    &B[(size_t)(k0 + br) * N + col0 + bc]);
        }
        __syncthreads();
#pragma unroll
        for (int kk = 0; kk < BK; kk++) {
            float a[8], b[8];
#pragma unroll
            for (int i = 0; i < 8; i++) a[i] = As[kk][ty * 8 + i];
#pragma unroll
            for (int j = 0; j < 8; j++) b[j] = Bs[kk][tx * 8 + j];
#pragma unroll
            for (int i = 0; i < 8; i++)
#pragma unroll
                for (int j = 0; j < 8; j++)
                    acc[i][j] = fmaf(a[i], b[j], acc[i][j]);
        }
        __syncthreads();
    }

#pragma unroll
    for (int i = 0; i < 8; i++) {
        int r = row0 + ty * 8 + i;
#pragma unroll
        for (int j = 0; j < 8; j += 4) {
            float4 v = make_float4(acc[i][j], acc[i][j + 1],
                                   acc[i][j + 2], acc[i][j + 3]);
            *reinterpret_cast<float4*>(&C[(size_t)r * N + col0 + tx * 8 + j]) = v;
        }
    }
}

// ---------------- flash attention: per (b,h), 64-query tiles ----------------
// Q,K,V,O layout: [b, n, h, e]  (row-n stride = HEADS*DHEAD = 1024 floats)
// Smem (floats): Qst[64][65] (e-major), Kst[64][65] (e-major),
//                Ssh[64][65] (S^T: [n][m]), Vs[64][64], mrow/lrow/arow[64]
__global__ __launch_bounds__(256) void flash_attn(const float* __restrict__ Q,
                                                  const float* __restrict__ K,
                                                  const float* __restrict__ V,
                                                  float* __restrict__ O) {
    extern __shared__ float sm[];
    float* Qst  = sm;                  // 64*65
    float* Kst  = Qst + 64 * 65;
    float* Ssh  = Kst + 64 * 65;
    float* Vs   = Ssh + 64 * 65;       // 64*64
    float* mrow = Vs + 64 * 64;
    float* lrow = mrow + 64;
    float* arow = lrow + 64;

    const int tid = threadIdx.x;
    const int tx = tid & 15;           // 16 across e (or n for S)
    const int ty = tid >> 4;           // 16 across m
    const int qt = blockIdx.x;         // query tile
    const int bh = blockIdx.y;
    const int b = bh >> 4, h = bh & 15;
    const int rs = HEADS * DHEAD;      // 1024
    const size_t base = ((size_t)(b * SEQ) * HEADS + h) * DHEAD;
    const float* Qb = Q + base;
    const float* Kb = K + base;
    const float* Vb = V + base;

    const float NEG_INF = __int_as_float(0xff800000);

    // Load Q tile, transposed to [e][m]
#pragma unroll
    for (int r = 0; r < 4; r++) {
        int i = tid + 256 * r;
        int n = i >> 4, e4 = (i & 15) * 4;
        float4 v = *reinterpret_cast<const float4*>(
            &Qb[(size_t)(qt * 64 + n) * rs + e4]);
        Qst[(e4 + 0) * 65 + n] = v.x;
        Qst[(e4 + 1) * 65 + n] = v.y;
        Qst[(e4 + 2) * 65 + n] = v.z;
        Qst[(e4 + 3) * 65 + n] = v.w;
    }
    if (tid < 64) { mrow[tid] = NEG_INF; lrow[tid] = 0.f; }
    float o[4][4] = {};
    __syncthreads();

    for (int jt = 0; jt < SEQ / 64; jt++) {
        // Load K tile (transposed [e][n]) and V tile (natural [n][e])
#pragma unroll
        for (int r = 0; r < 4; r++) {
            int i = tid + 256 * r;
            int n = i >> 4, e4 = (i & 15) * 4;
            float4 kv = *reinterpret_cast<const float4*>(
                &Kb[(size_t)(jt * 64 + n) * rs + e4]);
            Kst[(e4 + 0) * 65 + n] = kv.x;
            Kst[(e4 + 1) * 65 + n] = kv.y;
            Kst[(e4 + 2) * 65 + n] = kv.z;
            Kst[(e4 + 3) * 65 + n] = kv.w;
            float4 vv = *reinterpret_cast<const float4*>(
                &Vb[(size_t)(jt * 64 + n) * rs + e4]);
            *reinterpret_cast<float4*>(&Vs[n * 64 + e4]) = vv;
        }
        __syncthreads();

        // S = Q K^T : thread (ty,tx) owns m = ty*4+i, n = tx*4+j
        float s[4][4] = {};
#pragma unroll
        for (int kk = 0; kk < 64; kk++) {
            float a[4], bb[4];
#pragma unroll
            for (int i = 0; i < 4; i++) a[i] = Qst[kk * 65 + ty * 4 + i];
#pragma unroll
            for (int j = 0; j < 4; j++) bb[j] = Kst[kk * 65 + tx * 4 + j];
#pragma unroll
            for (int i = 0; i < 4; i++)
#pragma unroll
                for (int j = 0; j < 4; j++)
                    s[i][j] = fmaf(a[i], bb[j], s[i][j]);
        }
#pragma unroll
        for (int i = 0; i < 4; i++)
#pragma unroll
            for (int j = 0; j < 4; j++)
                Ssh[(tx * 4 + j) * 65 + ty * 4 + i] = s[i][j];
        __syncthreads();

        // Online softmax per query row (64 threads, one row each)
        if (tid < 64) {
            int m = tid;
            float mold = mrow[m];
            float mx = mold;
#pragma unroll 8
            for (int j = 0; j < 64; j++) mx = fmaxf(mx, Ssh[j * 65 + m]);
            float al = __expf(mold - mx);
            float sum = 0.f;
#pragma unroll 8
            for (int j = 0; j < 64; j++) {
                float p = __expf(Ssh[j * 65 + m] - mx);
                Ssh[j * 65 + m] = p;
                sum += p;
            }
            lrow[m] = lrow[m] * al + sum;
            mrow[m] = mx;
            arow[m] = al;
        }
        __syncthreads();

        // Rescale O and accumulate O += P V
#pragma unroll
        for (int i = 0; i < 4; i++) {
            float al = arow[ty * 4 + i];
#pragma unroll
            for (int j = 0; j < 4; j++) o[i][j] *= al;
        }
#pragma unroll
        for (int kk = 0; kk < 64; kk++) {
            float a[4], bb[4];
#pragma unroll
            for (int i = 0; i < 4; i++) a[i] = Ssh[kk * 65 + ty * 4 + i];
#pragma unroll
            for (int j = 0; j < 4; j++) bb[j] = Vs[kk * 64 + tx * 4 + j];
#pragma unroll
            for (int i = 0; i < 4; i++)
#pragma unroll
                for (int j = 0; j < 4; j++)
                    o[i][j] = fmaf(a[i], bb[j], o[i][j]);
        }
        __syncthreads();   // protect Kst/Vs/Ssh before next-iter loads
    }

    // Epilogue: normalize and write [b,n,h,e]
    float* Ob = O + base;
#pragma unroll
    for (int i = 0; i < 4; i++) {
        int m = ty * 4 + i;
        float inv = 1.f / lrow[m];
#pragma unroll
        for (int j = 0; j < 4; j++)
            Ob[(size_t)(qt * 64 + m) * rs + tx * 4 + j] = o[i][j] * inv;
    }
}

// ---------------- launch ----------------------------------------------------
extern "C" void kernel_launch(void* const* d_in, const int* in_sizes, int n_in,
                              void* d_out, int out_size) {
    const float* tokens = (const float*)d_in[0];
    const float* wq = (const float*)d_in[1];
    const float* wk = (const float*)d_in[2];
    const float* wv = (const float*)d_in[3];
    const float* wo = (const float*)d_in[4];   // [h,e,d] == [he=1024, d=1024] row-major
    float* out = (float*)d_out;

    float *q, *k, *v, *agg, *pwq, *pwk, *pwv;
    cudaGetSymbolAddress((void**)&q, g_q);
    cudaGetSymbolAddress((void**)&k, g_k);
    cudaGetSymbolAddress((void**)&v, g_v);
    cudaGetSymbolAddress((void**)&agg, g_agg);
    cudaGetSymbolAddress((void**)&pwq, g_wq);
    cudaGetSymbolAddress((void**)&pwk, g_wk);
    cudaGetSymbolAddress((void**)&pwv, g_wv);

    pack_w<<<(DIM * DIM + 255) / 256, 256>>>(wq, wk, wv);

    dim3 gp(DIM / BN, BS / BM);   // (8, 32)
    sgemm<<<gp, 256>>>(tokens, pwq, q, BS, DIM, DIM);
    sgemm<<<gp, 256>>>(tokens, pwk, k, BS, DIM, DIM);
    sgemm<<<gp, 256>>>(tokens, pwv, v, BS, DIM, DIM);

    size_t smem = (size_t)(3 * 64 * 65 + 64 * 64 + 3 * 64) * sizeof(float);
    cudaFuncSetAttribute(flash_attn, cudaFuncAttributeMaxDynamicSharedMemorySize,
                         (int)smem);
    flash_attn<<<dim3(SEQ / 64, BATCH * HEADS), 256, smem>>>(q, k, v, agg);

    sgemm<<<gp, 256>>>(agg, wo, out, BS, DIM, DIM);
}

// round 3
// speedup vs baseline: 1.3010x; 1.3010x over previous
#include <cuda_runtime.h>
#include <cuda_bf16.h>
#include <cstdint>

#define BATCH 2
#define SEQ 2048
#define DIM 1024
#define HEADS 16
#define DHEAD 64
#define BS (BATCH*SEQ)   // 4096

// ---------------- scratch (device globals; no allocations allowed) ----------
__device__ float g_q[BS*DIM];     // [b,n,h,e]
__device__ float g_k[BS*DIM];
__device__ float g_v[BS*DIM];
__device__ float g_agg[BS*DIM];
__device__ __nv_bfloat16 g_tokh[BS*DIM], g_tokl[BS*DIM];   // tokens split [M,K]
__device__ __nv_bfloat16 g_aggh[BS*DIM], g_aggl[BS*DIM];   // agg split    [M,K]
// weights packed to [N,K] (K-major) and split hi/lo
__device__ __nv_bfloat16 g_wqh[DIM*DIM], g_wql[DIM*DIM];
__device__ __nv_bfloat16 g_wkh[DIM*DIM], g_wkl[DIM*DIM];
__device__ __nv_bfloat16 g_wvh[DIM*DIM], g_wvl[DIM*DIM];
__device__ __nv_bfloat16 g_woh[DIM*DIM], g_wol[DIM*DIM];

// ---------------- helpers ----------------------------------------------------
__device__ __forceinline__ uint32_t smem_u32(const void* p) {
    uint32_t a;
    asm("{ .reg .u64 t; cvta.to.shared.u64 t, %1; cvt.u32.u64 %0, t; }"
        : "=r"(a) : "l"(p));
    return a;
}
#define SWZ128(o) ((o) ^ (((o) >> 3) & 0x70))

__device__ __forceinline__ void ldsm_x4(uint32_t* r, uint32_t addr) {
    asm volatile("ldmatrix.sync.aligned.m8n8.x4.shared.b16 {%0,%1,%2,%3}, [%4];"
                 : "=r"(r[0]), "=r"(r[1]), "=r"(r[2]), "=r"(r[3]) : "r"(addr));
}
__device__ __forceinline__ void ldsm_x2(uint32_t* r, uint32_t addr) {
    asm volatile("ldmatrix.sync.aligned.m8n8.x2.shared.b16 {%0,%1}, [%2];"
                 : "=r"(r[0]), "=r"(r[1]) : "r"(addr));
}
__device__ __forceinline__ void mma_bf16(float* c, const uint32_t* a, const uint32_t* b) {
    asm volatile(
        "mma.sync.aligned.m16n8k16.row.col.f32.bf16.bf16.f32 "
        "{%0,%1,%2,%3}, {%4,%5,%6,%7}, {%8,%9}, {%0,%1,%2,%3};"
        : "+f"(c[0]), "+f"(c[1]), "+f"(c[2]), "+f"(c[3])
        : "r"(a[0]), "r"(a[1]), "r"(a[2]), "r"(a[3]), "r"(b[0]), "r"(b[1]));
}

// ---------------- split / pack kernels ---------------------------------------
__device__ __forceinline__ void bsplit(float v, __nv_bfloat16& h, __nv_bfloat16& l) {
    h = __float2bfloat16(v);
    l = __float2bfloat16(v - __bfloat162float(h));
}

__global__ void split_act(const float4* __restrict__ x,
                          __nv_bfloat16* __restrict__ hi,
                          __nv_bfloat16* __restrict__ lo, int n4) {
    int i = blockIdx.x * blockDim.x + threadIdx.x;
    if (i >= n4) return;
    float4 v = x[i];
    __nv_bfloat16 h0, l0, h1, l1, h2, l2, h3, l3;
    bsplit(v.x, h0, l0); bsplit(v.y, h1, l1);
    bsplit(v.z, h2, l2); bsplit(v.w, h3, l3);
    __nv_bfloat162* H = reinterpret_cast<__nv_bfloat162*>(hi);
    __nv_bfloat162* L = reinterpret_cast<__nv_bfloat162*>(lo);
    H[2 * i] = __nv_bfloat162(h0, h1);
    H[2 * i + 1] = __nv_bfloat162(h2, h3);
    L[2 * i] = __nv_bfloat162(l0, l1);
    L[2 * i + 1] = __nv_bfloat162(l2, l3);
}

// wq/wk/wv: [h,d,e] -> [n=h*64+e, k=d]; wo: [he,d] -> [n=d, k=he]; split hi/lo
__global__ void pack_w(const float* __restrict__ wq, const float* __restrict__ wk,
                       const float* __restrict__ wv, const float* __restrict__ wo) {
    int idx = blockIdx.x * blockDim.x + threadIdx.x;
    if (idx >= DIM * DIM) return;
    int n = idx >> 10;
    int k = idx & 1023;
    int h = n >> 6, e = n & 63;
    int src = (h * DIM + k) * DHEAD + e;
    bsplit(wq[src] * 0.125f, g_wqh[idx], g_wql[idx]);   // SCALE = 64^-0.5
    bsplit(wk[src], g_wkh[idx], g_wkl[idx]);
    bsplit(wv[src], g_wvh[idx], g_wvl[idx]);
    bsplit(wo[k * DIM + n], g_woh[idx], g_wol[idx]);
}

// ---------------- bf16x3 GEMM via mma.sync (HMMA) ----------------------------
// C[M,N] = (Ah+Al)[M,K] * (Bh+Bl)[N,K]^T ; M=4096, N=1024, K=1024.
// CTA tile 128x64, BK=64. 8 warps, warp tile 32x32 = 2x4 m16n8k16.
// smem: Ah[128][128B] Al Bh[64][128B] Bl, SW128-swizzled; single buffer +
// register prefetch of next chunk.
#define GS_AH 0
#define GS_AL 16384
#define GS_BH 32768
#define GS_BL 40960
#define GS_TOTAL 49152

__global__ __launch_bounds__(256) void gemm_bf16x3(
    const __nv_bfloat16* __restrict__ Ah, const __nv_bfloat16* __restrict__ Al,
    const __nv_bfloat16* __restrict__ Bh, const __nv_bfloat16* __restrict__ Bl,
    float* __restrict__ C) {
    extern __shared__ char smem[];
    const uint32_t sb = smem_u32(smem);
    const int tid = threadIdx.x;
    const int lane = tid & 31;
    const int wid = tid >> 5;
    const int warp_m = wid & 3;          // 4 warps over M (32 rows each)
    const int warp_n = wid >> 2;         // 2 warps over N (32 cols each)
    const int row0 = blockIdx.y * 128;
    const int col0 = blockIdx.x * 64;

    // global sources (uint4 = 8 bf16), row stride = 1024 bf16 = 128 uint4
    const uint4* gA[2] = {reinterpret_cast<const uint4*>(Ah + (size_t)row0 * DIM),
                          reinterpret_cast<const uint4*>(Al + (size_t)row0 * DIM)};
    const uint4* gB[2] = {reinterpret_cast<const uint4*>(Bh + (size_t)col0 * DIM),
                          reinterpret_cast<const uint4*>(Bl + (size_t)col0 * DIM)};

    // this thread's two store slots per 512-uint4 half: idx, idx+256
    const int rA0 = tid >> 3, cA0 = tid & 7;                  // idx = tid
    const int rA1 = (tid + 256) >> 3, cA1 = tid & 7;          // idx = tid+256
    const int rB0 = rA0;                                      // B uses idx<512

    // ldmatrix source addresses (precomputed, swizzle applied per kstep)
    // A: row = warp_m*32 + i*16 + (lane&7) + ((lane>>3)&1)*8 ; colbase = ((lane>>4)&1)*16
    int arow[2], amask[2], abase[2];
    #pragma unroll
    for (int i = 0; i < 2; i++) {
        int r = warp_m * 32 + i * 16 + (lane & 7) + ((lane >> 3) & 1) * 8;
        arow[i] = r;
        amask[i] = (r & 7) << 4;
        abase[i] = r * 128 + ((lane >> 4) & 1) * 16;
    }
    // B: row(n) = warp_n*32 + j*8 + (lane&7) ; colbase = ((lane>>3)&1)*16
    int brow = warp_n * 32 + ((lane & 15) & 7);
    int bmaskbase = ((lane & 15) >> 3) * 16;

    float acc[2][4][4] = {};

    // prefetch chunk 0
    uint4 pa[2][4], pb[2][2];
    {
        const int k0u = 0;
#pragma unroll
        for (int m = 0; m < 2; m++) {
            pa[m][0] = gA[m][rA0 * 128 + k0u + cA0];
            pa[m][1] = gA[m][rA1 * 128 + k0u + cA1];
            pa[m][2] = gA[m][(rA0 + 64) * 128 + k0u + cA0];
            pa[m][3] = gA[m][(rA1 + 64) * 128 + k0u + cA1];
            pb[m][0] = gB[m][rB0 * 128 + k0u + cA0];
            pb[m][1] = gB[m][((tid + 256) >> 3) * 128 + k0u + cA1];   // rows 32..63
        }
    }

    for (int c = 0; c < 16; c++) {
        if (c) __syncthreads();   // previous compute done reading smem
        // store prefetched chunk
#pragma unroll
        for (int m = 0; m < 2; m++) {
            char* dA = smem + (m ? GS_AL : GS_AH);
            char* dB = smem + (m ? GS_BL : GS_BH);
            *reinterpret_cast<uint4*>(dA + SWZ128(rA0 * 128 + cA0 * 16)) = pa[m][0];
            *reinterpret_cast<uint4*>(dA + SWZ128(rA1 * 128 + cA1 * 16)) = pa[m][1];
            *reinterpret_cast<uint4*>(dA + SWZ128((rA0 + 64) * 128 + cA0 * 16)) = pa[m][2];
            *reinterpret_cast<uint4*>(dA + SWZ128((rA1 + 64) * 128 + cA1 * 16)) = pa[m][3];
            *reinterpret_cast<uint4*>(dB + SWZ128(rB0 * 128 + cA0 * 16)) = pb[m][0];
            *reinterpret_cast<uint4*>(dB + SWZ128(((tid + 256) >> 3) * 128 + cA1 * 16)) = pb[m][1];
        }
        __syncthreads();

        // prefetch next chunk (overlaps with MMA below)
        if (c < 15) {
            const int k0u = (c + 1) * 8;
#pragma unroll
            for (int m = 0; m < 2; m++) {
                pa[m][0] = gA[m][rA0 * 128 + k0u + cA0];
                pa[m][1] = gA[m][rA1 * 128 + k0u + cA1];
                pa[m][2] = gA[m][(rA0 + 64) * 128 + k0u + cA0];
                pa[m][3] = gA[m][(rA1 + 64) * 128 + k0u + cA1];
                pb[m][0] = gB[m][rB0 * 128 + k0u + cA0];
                pb[m][1] = gB[m][((tid + 256) >> 3) * 128 + k0u + cA1];
            }
        }

        // compute: 4 ksteps of k16
#pragma unroll
        for (int ks = 0; ks < 4; ks++) {
            uint32_t ah[2][4], al[2][4], bh[4][2], bl[4][2];
#pragma unroll
            for (int i = 0; i < 2; i++) {
                uint32_t offA = (abase[i] + ks * 32) ^ amask[i];
                ldsm_x4(ah[i], sb + GS_AH + offA);
                ldsm_x4(al[i], sb + GS_AL + offA);
            }
#pragma unroll
            for (int j = 0; j < 4; j++) {
                int r = brow + j * 8;
                uint32_t offB = (r * 128 + bmaskbase + ks * 32) ^ ((r & 7) << 4);
                ldsm_x2(bh[j], sb + GS_BH + offB);
                ldsm_x2(bl[j], sb + GS_BL + offB);
            }
#pragma unroll
            for (int i = 0; i < 2; i++)
#pragma unroll
                for (int j = 0; j < 4; j++) {
                    mma_bf16(acc[i][j], ah[i], bh[j]);
                    mma_bf16(acc[i][j], ah[i], bl[j]);
                    mma_bf16(acc[i][j], al[i], bh[j]);
                }
        }
    }

    // epilogue: fragment (l>>2 = row-in-8, l&3 = col pair)
    const int fr = lane >> 2, fc = (lane & 3) * 2;
#pragma unroll
    for (int i = 0; i < 2; i++) {
        int rbase = row0 + warp_m * 32 + i * 16 + fr;
#pragma unroll
        for (int j = 0; j < 4; j++) {
            int col = col0 + warp_n * 32 + j * 8 + fc;
            *reinterpret_cast<float2*>(&C[(size_t)rbase * DIM + col]) =
                make_float2(acc[i][j][0], acc[i][j][1]);
            *reinterpret_cast<float2*>(&C[(size_t)(rbase + 8) * DIM + col]) =
                make_float2(acc[i][j][2], acc[i][j][3]);
        }
    }
}

// ---------------- flash attention (unchanged, passing) -----------------------
__global__ __launch_bounds__(256) void flash_attn(const float* __restrict__ Q,
                                                  const float* __restrict__ K,
                                                  const float* __restrict__ V,
                                                  float* __restrict__ O) {
    extern __shared__ float sm[];
    float* Qst  = sm;
    float* Kst  = Qst + 64 * 65;
    float* Ssh  = Kst + 64 * 65;
    float* Vs   = Ssh + 64 * 65;
    float* mrow = Vs + 64 * 64;
    float* lrow = mrow + 64;
    float* arow = lrow + 64;

    const int tid = threadIdx.x;
    const int tx = tid & 15;
    const int ty = tid >> 4;
    const int qt = blockIdx.x;
    const int bh = blockIdx.y;
    const int b = bh >> 4, h = bh & 15;
    const int rs = HEADS * DHEAD;
    const size_t base = ((size_t)(b * SEQ) * HEADS + h) * DHEAD;
    const float* Qb = Q + base;
    const float* Kb = K + base;
    const float* Vb = V + base;

    const float NEG_INF = __int_as_float(0xff800000);

#pragma unroll
    for (int r = 0; r < 4; r++) {
        int i = tid + 256 * r;
        int n = i >> 4, e4 = (i & 15) * 4;
        float4 v = *reinterpret_cast<const float4*>(&Qb[(size_t)(qt * 64 + n) * rs + e4]);
        Qst[(e4 + 0) * 65 + n] = v.x;
        Qst[(e4 + 1) * 65 + n] = v.y;
        Qst[(e4 + 2) * 65 + n] = v.z;
        Qst[(e4 + 3) * 65 + n] = v.w;
    }
    if (tid < 64) { mrow[tid] = NEG_INF; lrow[tid] = 0.f; }
    float o[4][4] = {};
    __syncthreads();

    for (int jt = 0; jt < SEQ / 64; jt++) {
#pragma unroll
        for (int r = 0; r < 4; r++) {
            int i = tid + 256 * r;
            int n = i >> 4, e4 = (i & 15) * 4;
            float4 kv = *reinterpret_cast<const float4*>(&Kb[(size_t)(jt * 64 + n) * rs + e4]);
            Kst[(e4 + 0) * 65 + n] = kv.x;
            Kst[(e4 + 1) * 65 + n] = kv.y;
            Kst[(e4 + 2) * 65 + n] = kv.z;
            Kst[(e4 + 3) * 65 + n] = kv.w;
            float4 vv = *reinterpret_cast<const float4*>(&Vb[(size_t)(jt * 64 + n) * rs + e4]);
            *reinterpret_cast<float4*>(&Vs[n * 64 + e4]) = vv;
        }
        __syncthreads();

        float s[4][4] = {};
#pragma unroll
        for (int kk = 0; kk < 64; kk++) {
            float a[4], bb[4];
#pragma unroll
            for (int i = 0; i < 4; i++) a[i] = Qst[kk * 65 + ty * 4 + i];
#pragma unroll
            for (int j = 0; j < 4; j++) bb[j] = Kst[kk * 65 + tx * 4 + j];
#pragma unroll
            for (int i = 0; i < 4; i++)
#pragma unroll
                for (int j = 0; j < 4; j++)
                    s[i][j] = fmaf(a[i], bb[j], s[i][j]);
        }
#pragma unroll
        for (int i = 0; i < 4; i++)
#pragma unroll
            for (int j = 0; j < 4; j++)
                Ssh[(tx * 4 + j) * 65 + ty * 4 + i] = s[i][j];
        __syncthreads();

        if (tid < 64) {
            int m = tid;
            float mold = mrow[m];
            float mx = mold;
#pragma unroll 8
            for (int j = 0; j < 64; j++) mx = fmaxf(mx, Ssh[j * 65 + m]);
            float al = __expf(mold - mx);
            float sum = 0.f;
#pragma unroll 8
            for (int j = 0; j < 64; j++) {
                float p = __expf(Ssh[j * 65 + m] - mx);
                Ssh[j * 65 + m] = p;
                sum += p;
            }
            lrow[m] = lrow[m] * al + sum;
            mrow[m] = mx;
            arow[m] = al;
        }
        __syncthreads();

#pragma unroll
        for (int i = 0; i < 4; i++) {
            float al = arow[ty * 4 + i];
#pragma unroll
            for (int j = 0; j < 4; j++) o[i][j] *= al;
        }
#pragma unroll
        for (int kk = 0; kk < 64; kk++) {
            float a[4], bb[4];
#pragma unroll
            for (int i = 0; i < 4; i++) a[i] = Ssh[kk * 65 + ty * 4 + i];
#pragma unroll
            for (int j = 0; j < 4; j++) bb[j] = Vs[kk * 64 + tx * 4 + j];
#pragma unroll
            for (int i = 0; i < 4; i++)
#pragma unroll
                for (int j = 0; j < 4; j++)
                    o[i][j] = fmaf(a[i], bb[j], o[i][j]);
        }
        __syncthreads();
    }

    float* Ob = O + base;
#pragma unroll
    for (int i = 0; i < 4; i++) {
        int m = ty * 4 + i;
        float inv = 1.f / lrow[m];
#pragma unroll
        for (int j = 0; j < 4; j++)
            Ob[(size_t)(qt * 64 + m) * rs + tx * 4 + j] = o[i][j] * inv;
    }
}

// ---------------- launch ------------------------------------------------------
extern "C" void kernel_launch(void* const* d_in, const int* in_sizes, int n_in,
                              void* d_out, int out_size) {
    const float* tokens = (const float*)d_in[0];
    const float* wq = (const float*)d_in[1];
    const float* wk = (const float*)d_in[2];
    const float* wv = (const float*)d_in[3];
    const float* wo = (const float*)d_in[4];
    float* out = (float*)d_out;

    float *q, *k, *v, *agg;
    __nv_bfloat16 *tokh, *tokl, *aggh, *aggl;
    __nv_bfloat16 *wqh, *wql, *wkh, *wkl, *wvh, *wvl, *woh, *wol;
    cudaGetSymbolAddress((void**)&q, g_q);
    cudaGetSymbolAddress((void**)&k, g_k);
    cudaGetSymbolAddress((void**)&v, g_v);
    cudaGetSymbolAddress((void**)&agg, g_agg);
    cudaGetSymbolAddress((void**)&tokh, g_tokh);
    cudaGetSymbolAddress((void**)&tokl, g_tokl);
    cudaGetSymbolAddress((void**)&aggh, g_aggh);
    cudaGetSymbolAddress((void**)&aggl, g_aggl);
    cudaGetSymbolAddress((void**)&wqh, g_wqh);
    cudaGetSymbolAddress((void**)&wql, g_wql);
    cudaGetSymbolAddress((void**)&wkh, g_wkh);
    cudaGetSymbolAddress((void**)&wkl, g_wkl);
    cudaGetSymbolAddress((void**)&wvh, g_wvh);
    cudaGetSymbolAddress((void**)&wvl, g_wvl);
    cudaGetSymbolAddress((void**)&woh, g_woh);
    cudaGetSymbolAddress((void**)&wol, g_wol);

    split_act<<<(BS * DIM / 4 + 255) / 256, 256>>>(
        (const float4*)tokens, tokh, tokl, BS * DIM / 4);
    pack_w<<<(DIM * DIM + 255) / 256, 256>>>(wq, wk, wv, wo);

    cudaFuncSetAttribute(gemm_bf16x3, cudaFuncAttributeMaxDynamicSharedMemorySize,
                         GS_TOTAL);
    dim3 gp(DIM / 64, BS / 128);   // (16, 32)
    gemm_bf16x3<<<gp, 256, GS_TOTAL>>>(tokh, tokl, wqh, wql, q);
    gemm_bf16x3<<<gp, 256, GS_TOTAL>>>(tokh, tokl, wkh, wkl, k);
    gemm_bf16x3<<<gp, 256, GS_TOTAL>>>(tokh, tokl, wvh, wvl, v);

    size_t smem = (size_t)(3 * 64 * 65 + 64 * 64 + 3 * 64) * sizeof(float);
    cudaFuncSetAttribute(flash_attn, cudaFuncAttributeMaxDynamicSharedMemorySize,
                         (int)smem);
    flash_attn<<<dim3(SEQ / 64, BATCH * HEADS), 256, smem>>>(q, k, v, agg);

    split_act<<<(BS * DIM / 4 + 255) / 256, 256>>>(
        (const float4*)agg, aggh, aggl, BS * DIM / 4);
    gemm_bf16x3<<<gp, 256, GS_TOTAL>>>(aggh, aggl, woh, wol, out);
}

// round 4
// speedup vs baseline: 2.2652x; 1.7410x over previous
#include <cuda_runtime.h>
#include <cuda_bf16.h>
#include <cstdint>

#define BATCH 2
#define SEQ 2048
#define DIM 1024
#define HEADS 16
#define DHEAD 64
#define BS (BATCH*SEQ)   // 4096

// ---------------- scratch (device globals; no allocations allowed) ----------
__device__ __nv_bfloat16 g_tokh[BS*DIM], g_tokl[BS*DIM];   // tokens split [M,K]
__device__ __nv_bfloat16 g_qh[BS*DIM], g_ql[BS*DIM];       // q split [b,n,h,e]
__device__ __nv_bfloat16 g_kh[BS*DIM], g_kl[BS*DIM];
__device__ __nv_bfloat16 g_vh[BS*DIM], g_vl[BS*DIM];
__device__ __nv_bfloat16 g_aggh[BS*DIM], g_aggl[BS*DIM];   // attn out split
__device__ __nv_bfloat16 g_wqh[DIM*DIM], g_wql[DIM*DIM];   // weights [N,K] split
__device__ __nv_bfloat16 g_wkh[DIM*DIM], g_wkl[DIM*DIM];
__device__ __nv_bfloat16 g_wvh[DIM*DIM], g_wvl[DIM*DIM];
__device__ __nv_bfloat16 g_woh[DIM*DIM], g_wol[DIM*DIM];

// ---------------- helpers ----------------------------------------------------
__device__ __forceinline__ uint32_t smem_u32(const void* p) {
    uint32_t a;
    asm("{ .reg .u64 t; cvta.to.shared.u64 t, %1; cvt.u32.u64 %0, t; }"
        : "=r"(a) : "l"(p));
    return a;
}
#define SWZ128(o) ((o) ^ (((o) >> 3) & 0x70))

__device__ __forceinline__ void ldsm_x4(uint32_t* r, uint32_t addr) {
    asm volatile("ldmatrix.sync.aligned.m8n8.x4.shared.b16 {%0,%1,%2,%3}, [%4];"
                 : "=r"(r[0]), "=r"(r[1]), "=r"(r[2]), "=r"(r[3]) : "r"(addr));
}
__device__ __forceinline__ void ldsm_x2(uint32_t* r, uint32_t addr) {
    asm volatile("ldmatrix.sync.aligned.m8n8.x2.shared.b16 {%0,%1}, [%2];"
                 : "=r"(r[0]), "=r"(r[1]) : "r"(addr));
}
__device__ __forceinline__ void ldsm_x2t(uint32_t* r, uint32_t addr) {
    asm volatile("ldmatrix.sync.aligned.m8n8.x2.trans.shared.b16 {%0,%1}, [%2];"
                 : "=r"(r[0]), "=r"(r[1]) : "r"(addr));
}
__device__ __forceinline__ void mma_bf16(float* c, const uint32_t* a, const uint32_t* b) {
    asm volatile(
        "mma.sync.aligned.m16n8k16.row.col.f32.bf16.bf16.f32 "
        "{%0,%1,%2,%3}, {%4,%5,%6,%7}, {%8,%9}, {%0,%1,%2,%3};"
        : "+f"(c[0]), "+f"(c[1]), "+f"(c[2]), "+f"(c[3])
        : "r"(a[0]), "r"(a[1]), "r"(a[2]), "r"(a[3]), "r"(b[0]), "r"(b[1]));
}
__device__ __forceinline__ void bsplit(float v, __nv_bfloat16& h, __nv_bfloat16& l) {
    h = __float2bfloat16(v);
    l = __float2bfloat16(v - __bfloat162float(h));
}
__device__ __forceinline__ __nv_bfloat162 mk2(__nv_bfloat16 a, __nv_bfloat16 b) {
    __nv_bfloat162 t; t.x = a; t.y = b; return t;
}

// ---------------- split / pack kernels ---------------------------------------
__global__ void split_act(const float4* __restrict__ x,
                          __nv_bfloat16* __restrict__ hi,
                          __nv_bfloat16* __restrict__ lo, int n4) {
    int i = blockIdx.x * blockDim.x + threadIdx.x;
    if (i >= n4) return;
    float4 v = x[i];
    __nv_bfloat16 h0, l0, h1, l1, h2, l2, h3, l3;
    bsplit(v.x, h0, l0); bsplit(v.y, h1, l1);
    bsplit(v.z, h2, l2); bsplit(v.w, h3, l3);
    __nv_bfloat162* H = reinterpret_cast<__nv_bfloat162*>(hi);
    __nv_bfloat162* L = reinterpret_cast<__nv_bfloat162*>(lo);
    H[2 * i] = mk2(h0, h1);
    H[2 * i + 1] = mk2(h2, h3);
    L[2 * i] = mk2(l0, l1);
    L[2 * i + 1] = mk2(l2, l3);
}

// wq/wk/wv: [h,d,e] -> [n=h*64+e, k=d]; wo: [he,d] -> [n=d, k=he]; split hi/lo
__global__ void pack_w(const float* __restrict__ wq, const float* __restrict__ wk,
                       const float* __restrict__ wv, const float* __restrict__ wo) {
    int idx = blockIdx.x * blockDim.x + threadIdx.x;
    if (idx >= DIM * DIM) return;
    int n = idx >> 10;
    int k = idx & 1023;
    int h = n >> 6, e = n & 63;
    int src = (h * DIM + k) * DHEAD + e;
    bsplit(wq[src] * 0.125f, g_wqh[idx], g_wql[idx]);   // SCALE = 64^-0.5
    bsplit(wk[src], g_wkh[idx], g_wkl[idx]);
    bsplit(wv[src], g_wvh[idx], g_wvl[idx]);
    bsplit(wo[k * DIM + n], g_woh[idx], g_wol[idx]);
}

// ---------------- bf16x3 GEMM via mma.sync (HMMA) ----------------------------
// C[M,N] = (Ah+Al)[M,K] * (Bh+Bl)[N,K]^T ; M=4096, N=1024, K=1024.
// CTA tile 128x64, BK=64. 8 warps, warp tile 32x32 = 2x4 m16n8k16.
// SPLIT=true: write bf16 hi/lo outputs; false: fp32 C.
#define GS_AH 0
#define GS_AL 16384
#define GS_BH 32768
#define GS_BL 40960
#define GS_TOTAL 49152

template <bool SPLIT>
__global__ __launch_bounds__(256) void gemm_bf16x3(
    const __nv_bfloat16* __restrict__ Ah, const __nv_bfloat16* __restrict__ Al,
    const __nv_bfloat16* __restrict__ Bh, const __nv_bfloat16* __restrict__ Bl,
    float* __restrict__ C, __nv_bfloat16* __restrict__ Ch,
    __nv_bfloat16* __restrict__ Cl) {
    extern __shared__ char smem[];
    const uint32_t sb = smem_u32(smem);
    const int tid = threadIdx.x;
    const int lane = tid & 31;
    const int wid = tid >> 5;
    const int warp_m = wid & 3;
    const int warp_n = wid >> 2;
    const int row0 = blockIdx.y * 128;
    const int col0 = blockIdx.x * 64;

    const uint4* gA[2] = {reinterpret_cast<const uint4*>(Ah + (size_t)row0 * DIM),
                          reinterpret_cast<const uint4*>(Al + (size_t)row0 * DIM)};
    const uint4* gB[2] = {reinterpret_cast<const uint4*>(Bh + (size_t)col0 * DIM),
                          reinterpret_cast<const uint4*>(Bl + (size_t)col0 * DIM)};

    const int rA0 = tid >> 3, cA0 = tid & 7;
    const int rA1 = (tid + 256) >> 3, cA1 = tid & 7;
    const int rB0 = rA0;

    int amask[2], abase[2];
#pragma unroll
    for (int i = 0; i < 2; i++) {
        int r = warp_m * 32 + i * 16 + (lane & 15);
        amask[i] = (r & 7) << 4;
        abase[i] = r * 128 + ((lane >> 4) & 1) * 16;
    }
    int brow = warp_n * 32 + ((lane & 15) & 7);
    int bmaskbase = ((lane & 15) >> 3) * 16;

    float acc[2][4][4] = {};

    uint4 pa[2][4], pb[2][2];
    {
#pragma unroll
        for (int m = 0; m < 2; m++) {
            pa[m][0] = gA[m][rA0 * 128 + cA0];
            pa[m][1] = gA[m][rA1 * 128 + cA1];
            pa[m][2] = gA[m][(rA0 + 64) * 128 + cA0];
            pa[m][3] = gA[m][(rA1 + 64) * 128 + cA1];
            pb[m][0] = gB[m][rB0 * 128 + cA0];
            pb[m][1] = gB[m][((tid + 256) >> 3) * 128 + cA1];
        }
    }

    for (int c = 0; c < 16; c++) {
        if (c) __syncthreads();
#pragma unroll
        for (int m = 0; m < 2; m++) {
            char* dA = smem + (m ? GS_AL : GS_AH);
            char* dB = smem + (m ? GS_BL : GS_BH);
            *reinterpret_cast<uint4*>(dA + SWZ128(rA0 * 128 + cA0 * 16)) = pa[m][0];
            *reinterpret_cast<uint4*>(dA + SWZ128(rA1 * 128 + cA1 * 16)) = pa[m][1];
            *reinterpret_cast<uint4*>(dA + SWZ128((rA0 + 64) * 128 + cA0 * 16)) = pa[m][2];
            *reinterpret_cast<uint4*>(dA + SWZ128((rA1 + 64) * 128 + cA1 * 16)) = pa[m][3];
            *reinterpret_cast<uint4*>(dB + SWZ128(rB0 * 128 + cA0 * 16)) = pb[m][0];
            *reinterpret_cast<uint4*>(dB + SWZ128(((tid + 256) >> 3) * 128 + cA1 * 16)) = pb[m][1];
        }
        __syncthreads();

        if (c < 15) {
            const int k0u = (c + 1) * 8;
#pragma unroll
            for (int m = 0; m < 2; m++) {
                pa[m][0] = gA[m][rA0 * 128 + k0u + cA0];
                pa[m][1] = gA[m][rA1 * 128 + k0u + cA1];
                pa[m][2] = gA[m][(rA0 + 64) * 128 + k0u + cA0];
                pa[m][3] = gA[m][(rA1 + 64) * 128 + k0u + cA1];
                pb[m][0] = gB[m][rB0 * 128 + k0u + cA0];
                pb[m][1] = gB[m][((tid + 256) >> 3) * 128 + k0u + cA1];
            }
        }

#pragma unroll
        for (int ks = 0; ks < 4; ks++) {
            uint32_t ah[2][4], al[2][4], bh[4][2], bl[4][2];
#pragma unroll
            for (int i = 0; i < 2; i++) {
                uint32_t offA = (abase[i] + ks * 32) ^ amask[i];
                ldsm_x4(ah[i], sb + GS_AH + offA);
                ldsm_x4(al[i], sb + GS_AL + offA);
            }
#pragma unroll
            for (int j = 0; j < 4; j++) {
                int r = brow + j * 8;
                uint32_t offB = (r * 128 + bmaskbase + ks * 32) ^ ((r & 7) << 4);
                ldsm_x2(bh[j], sb + GS_BH + offB);
                ldsm_x2(bl[j], sb + GS_BL + offB);
            }
#pragma unroll
            for (int i = 0; i < 2; i++)
#pragma unroll
                for (int j = 0; j < 4; j++) {
                    mma_bf16(acc[i][j], ah[i], bh[j]);
                    mma_bf16(acc[i][j], ah[i], bl[j]);
                    mma_bf16(acc[i][j], al[i], bh[j]);
                }
        }
    }

    const int fr = lane >> 2, fc = (lane & 3) * 2;
#pragma unroll
    for (int i = 0; i < 2; i++) {
        int rbase = row0 + warp_m * 32 + i * 16 + fr;
#pragma unroll
        for (int j = 0; j < 4; j++) {
            int col = col0 + warp_n * 32 + j * 8 + fc;
            if (SPLIT) {
                __nv_bfloat16 h0, l0, h1, l1;
                bsplit(acc[i][j][0], h0, l0); bsplit(acc[i][j][1], h1, l1);
                *reinterpret_cast<__nv_bfloat162*>(&Ch[(size_t)rbase * DIM + col]) = mk2(h0, h1);
                *reinterpret_cast<__nv_bfloat162*>(&Cl[(size_t)rbase * DIM + col]) = mk2(l0, l1);
                bsplit(acc[i][j][2], h0, l0); bsplit(acc[i][j][3], h1, l1);
                *reinterpret_cast<__nv_bfloat162*>(&Ch[(size_t)(rbase + 8) * DIM + col]) = mk2(h0, h1);
                *reinterpret_cast<__nv_bfloat162*>(&Cl[(size_t)(rbase + 8) * DIM + col]) = mk2(l0, l1);
            } else {
                *reinterpret_cast<float2*>(&C[(size_t)rbase * DIM + col]) =
                    make_float2(acc[i][j][0], acc[i][j][1]);
                *reinterpret_cast<float2*>(&C[(size_t)(rbase + 8) * DIM + col]) =
                    make_float2(acc[i][j][2], acc[i][j][3]);
            }
        }
    }
}

// ---------------- flash attention via mma.sync, bf16x3 -----------------------
// Per (b,h): 128-query tile x 64-KV tiles. 8 warps: 4 over M(32), 2 over N(32).
// smem: Qh/Ql[128][64], Kh/Kl[64][64], Vh/Vl[64][64], Ph/Pl[128][64] (bf16,
// SW128 swizzled, 128B rows), plus softmax state.
#define FA_QH 0
#define FA_QL 16384
#define FA_KH 32768
#define FA_KL 40960
#define FA_VH 49152
#define FA_VL 57344
#define FA_PH 65536
#define FA_PL 81920
#define FA_MR 98304
#define FA_LR (98304+512)
#define FA_RM (98304+1024)
#define FA_RL (98304+2048)
#define FA_TOTAL (98304+3072)

__global__ __launch_bounds__(256) void flash_attn_mma(
    const __nv_bfloat16* __restrict__ Qh, const __nv_bfloat16* __restrict__ Ql,
    const __nv_bfloat16* __restrict__ Kh, const __nv_bfloat16* __restrict__ Kl,
    const __nv_bfloat16* __restrict__ Vh, const __nv_bfloat16* __restrict__ Vl,
    __nv_bfloat16* __restrict__ Oh, __nv_bfloat16* __restrict__ Ol) {
    extern __shared__ char smem[];
    const uint32_t sb = smem_u32(smem);
    const int tid = threadIdx.x, lane = tid & 31, wid = tid >> 5;
    const int wm = wid & 3, wn = wid >> 2;
    const int qt = blockIdx.x, bh = blockIdx.y;
    const int b = bh >> 4, h = bh & 15;
    const size_t base = ((size_t)(b * SEQ) * HEADS + h) * DHEAD;
    const uint4* Qhp = reinterpret_cast<const uint4*>(Qh + base);
    const uint4* Qlp = reinterpret_cast<const uint4*>(Ql + base);
    const uint4* Khp = reinterpret_cast<const uint4*>(Kh + base);
    const uint4* Klp = reinterpret_cast<const uint4*>(Kl + base);
    const uint4* Vhp = reinterpret_cast<const uint4*>(Vh + base);
    const uint4* Vlp = reinterpret_cast<const uint4*>(Vl + base);
    float* mrow = reinterpret_cast<float*>(smem + FA_MR);
    float* lrow = reinterpret_cast<float*>(smem + FA_LR);
    float* redm = reinterpret_cast<float*>(smem + FA_RM);   // [2][128]
    float* redl = reinterpret_cast<float*>(smem + FA_RL);   // [2][128]

    // load Q tile (both splits)
#pragma unroll
    for (int r4 = 0; r4 < 4; r4++) {
        int idx = tid + 256 * r4;                 // 0..1023
        int row = idx >> 3, c8 = idx & 7;
        uint32_t off = SWZ128(row * 128 + c8 * 16);
        int g = (qt * 128 + row) * 128 + c8;      // uint4 index (row stride 1024 bf16)
        *reinterpret_cast<uint4*>(smem + FA_QH + off) = Qhp[g];
        *reinterpret_cast<uint4*>(smem + FA_QL + off) = Qlp[g];
    }
    if (tid < 128) { mrow[tid] = -1e30f; lrow[tid] = 0.f; }

    float o[2][4][4] = {};
    const int fr = lane >> 2, fc = (lane & 3) * 2;
    const int aRow = lane & 15, aCol = (lane >> 4) * 16;   // A-operand pattern (bytes)
    const int l16 = lane & 15;
    const int bkRow = l16 & 7, bkHalf = (l16 >> 3) * 16;   // B-operand (K) pattern
    __syncthreads();

    for (int jt = 0; jt < SEQ / 64; jt++) {
        // load K/V tiles (both splits)
#pragma unroll
        for (int r4 = 0; r4 < 2; r4++) {
            int idx = tid + 256 * r4;             // 0..511
            int row = idx >> 3, c8 = idx & 7;
            uint32_t off = SWZ128(row * 128 + c8 * 16);
            int g = (jt * 64 + row) * 128 + c8;
            *reinterpret_cast<uint4*>(smem + FA_KH + off) = Khp[g];
            *reinterpret_cast<uint4*>(smem + FA_KL + off) = Klp[g];
            *reinterpret_cast<uint4*>(smem + FA_VH + off) = Vhp[g];
            *reinterpret_cast<uint4*>(smem + FA_VL + off) = Vlp[g];
        }
        __syncthreads();

        // S = Q K^T (x3)
        float s[2][4][4] = {};
#pragma unroll
        for (int ks = 0; ks < 4; ks++) {
            uint32_t ah[2][4], al[2][4], bhr[4][2], blr[4][2];
#pragma unroll
            for (int i = 0; i < 2; i++) {
                uint32_t off = SWZ128((wm * 32 + i * 16 + aRow) * 128 + ks * 32 + aCol);
                ldsm_x4(ah[i], sb + FA_QH + off);
                ldsm_x4(al[i], sb + FA_QL + off);
            }
#pragma unroll
            for (int j = 0; j < 4; j++) {
                uint32_t off = SWZ128((wn * 32 + j * 8 + bkRow) * 128 + ks * 32 + bkHalf);
                ldsm_x2(bhr[j], sb + FA_KH + off);
                ldsm_x2(blr[j], sb + FA_KL + off);
            }
#pragma unroll
            for (int i = 0; i < 2; i++)
#pragma unroll
                for (int j = 0; j < 4; j++) {
                    mma_bf16(s[i][j], ah[i], bhr[j]);
                    mma_bf16(s[i][j], ah[i], blr[j]);
                    mma_bf16(s[i][j], al[i], bhr[j]);
                }
        }

        // softmax phase 1: per-warp row max -> redm
#pragma unroll
        for (int i = 0; i < 2; i++)
#pragma unroll
            for (int hf = 0; hf < 2; hf++) {
                float v = s[i][0][hf * 2];
#pragma unroll
                for (int j = 0; j < 4; j++) {
                    v = fmaxf(v, s[i][j][hf * 2]);
                    v = fmaxf(v, s[i][j][hf * 2 + 1]);
                }
                v = fmaxf(v, __shfl_xor_sync(0xffffffffu, v, 1));
                v = fmaxf(v, __shfl_xor_sync(0xffffffffu, v, 2));
                if ((lane & 3) == 0)
                    redm[wn * 128 + wm * 32 + i * 16 + hf * 8 + fr] = v;
            }
        __syncthreads();

        // phase 2: alpha, exp, write P, partial row sums -> redl
        float alpha[2][2], mnew[2][2], rsum[2][2];
#pragma unroll
        for (int i = 0; i < 2; i++)
#pragma unroll
            for (int hf = 0; hf < 2; hf++) {
                int r = wm * 32 + i * 16 + hf * 8 + fr;
                float mo = mrow[r];
                float mn = fmaxf(mo, fmaxf(redm[r], redm[128 + r]));
                mnew[i][hf] = mn;
                alpha[i][hf] = __expf(mo - mn);
                rsum[i][hf] = 0.f;
            }
#pragma unroll
        for (int i = 0; i < 2; i++)
#pragma unroll
            for (int j = 0; j < 4; j++)
#pragma unroll
                for (int hf = 0; hf < 2; hf++) {
                    float p0 = __expf(s[i][j][hf * 2] - mnew[i][hf]);
                    float p1 = __expf(s[i][j][hf * 2 + 1] - mnew[i][hf]);
                    rsum[i][hf] += p0 + p1;
                    __nv_bfloat16 h0, l0, h1, l1;
                    bsplit(p0, h0, l0); bsplit(p1, h1, l1);
                    int r = wm * 32 + i * 16 + hf * 8 + fr;
                    uint32_t off = SWZ128(r * 128 + (wn * 32 + j * 8 + fc) * 2);
                    *reinterpret_cast<__nv_bfloat162*>(smem + FA_PH + off) = mk2(h0, h1);
                    *reinterpret_cast<__nv_bfloat162*>(smem + FA_PL + off) = mk2(l0, l1);
                }
#pragma unroll
        for (int i = 0; i < 2; i++)
#pragma unroll
            for (int hf = 0; hf < 2; hf++) {
                float v = rsum[i][hf];
                v += __shfl_xor_sync(0xffffffffu, v, 1);
                v += __shfl_xor_sync(0xffffffffu, v, 2);
                if ((lane & 3) == 0)
                    redl[wn * 128 + wm * 32 + i * 16 + hf * 8 + fr] = v;
            }
        __syncthreads();

        // state update (race-free: mrow/lrow next read after 2 more syncs)
        if (tid < 128) {
            float mo = mrow[tid];
            float mn = fmaxf(mo, fmaxf(redm[tid], redm[128 + tid]));
            lrow[tid] = lrow[tid] * __expf(mo - mn) + redl[tid] + redl[128 + tid];
            mrow[tid] = mn;
        }
        // rescale O
#pragma unroll
        for (int i = 0; i < 2; i++)
#pragma unroll
            for (int j = 0; j < 4; j++)
#pragma unroll
                for (int hf = 0; hf < 2; hf++) {
                    o[i][j][hf * 2] *= alpha[i][hf];
                    o[i][j][hf * 2 + 1] *= alpha[i][hf];
                }
        // O += P V (x3), V via ldmatrix.trans
#pragma unroll
        for (int ks = 0; ks < 4; ks++) {
            uint32_t ph[2][4], pl[2][4], vh[4][2], vl[4][2];
#pragma unroll
            for (int i = 0; i < 2; i++) {
                uint32_t off = SWZ128((wm * 32 + i * 16 + aRow) * 128 + ks * 32 + aCol);
                ldsm_x4(ph[i], sb + FA_PH + off);
                ldsm_x4(pl[i], sb + FA_PL + off);
            }
#pragma unroll
            for (int j = 0; j < 4; j++) {
                uint32_t off = SWZ128((ks * 16 + l16) * 128 + (wn * 32 + j * 8) * 2);
                ldsm_x2t(vh[j], sb + FA_VH + off);
                ldsm_x2t(vl[j], sb + FA_VL + off);
            }
#pragma unroll
            for (int i = 0; i < 2; i++)
#pragma unroll
                for (int j = 0; j < 4; j++) {
                    mma_bf16(o[i][j], ph[i], vh[j]);
                    mma_bf16(o[i][j], ph[i], vl[j]);
                    mma_bf16(o[i][j], pl[i], vh[j]);
                }
        }
        __syncthreads();
    }

    // epilogue: normalize, split, store [b,n,h,e]
#pragma unroll
    for (int i = 0; i < 2; i++)
#pragma unroll
        for (int hf = 0; hf < 2; hf++) {
            int r = wm * 32 + i * 16 + hf * 8 + fr;
            float inv = 1.f / lrow[r];
#pragma unroll
            for (int j = 0; j < 4; j++) {
                float v0 = o[i][j][hf * 2] * inv;
                float v1 = o[i][j][hf * 2 + 1] * inv;
                __nv_bfloat16 h0, l0, h1, l1;
                bsplit(v0, h0, l0); bsplit(v1, h1, l1);
                size_t off = (size_t)(qt * 128 + r) * 1024 + wn * 32 + j * 8 + fc;
                *reinterpret_cast<__nv_bfloat162*>(Oh + base + off) = mk2(h0, h1);
                *reinterpret_cast<__nv_bfloat162*>(Ol + base + off) = mk2(l0, l1);
            }
        }
}

// ---------------- launch ------------------------------------------------------
extern "C" void kernel_launch(void* const* d_in, const int* in_sizes, int n_in,
                              void* d_out, int out_size) {
    const float* tokens = (const float*)d_in[0];
    const float* wq = (const float*)d_in[1];
    const float* wk = (const float*)d_in[2];
    const float* wv = (const float*)d_in[3];
    const float* wo = (const float*)d_in[4];
    float* out = (float*)d_out;

    __nv_bfloat16 *tokh, *tokl, *qh, *ql, *kh, *kl, *vh, *vl, *aggh, *aggl;
    __nv_bfloat16 *wqh, *wql, *wkh, *wkl, *wvh, *wvl, *woh, *wol;
    cudaGetSymbolAddress((void**)&tokh, g_tokh);
    cudaGetSymbolAddress((void**)&tokl, g_tokl);
    cudaGetSymbolAddress((void**)&qh, g_qh);
    cudaGetSymbolAddress((void**)&ql, g_ql);
    cudaGetSymbolAddress((void**)&kh, g_kh);
    cudaGetSymbolAddress((void**)&kl, g_kl);
    cudaGetSymbolAddress((void**)&vh, g_vh);
    cudaGetSymbolAddress((void**)&vl, g_vl);
    cudaGetSymbolAddress((void**)&aggh, g_aggh);
    cudaGetSymbolAddress((void**)&aggl, g_aggl);
    cudaGetSymbolAddress((void**)&wqh, g_wqh);
    cudaGetSymbolAddress((void**)&wql, g_wql);
    cudaGetSymbolAddress((void**)&wkh, g_wkh);
    cudaGetSymbolAddress((void**)&wkl, g_wkl);
    cudaGetSymbolAddress((void**)&wvh, g_wvh);
    cudaGetSymbolAddress((void**)&wvl, g_wvl);
    cudaGetSymbolAddress((void**)&woh, g_woh);
    cudaGetSymbolAddress((void**)&wol, g_wol);

    split_act<<<(BS * DIM / 4 + 255) / 256, 256>>>(
        (const float4*)tokens, tokh, tokl, BS * DIM / 4);
    pack_w<<<(DIM * DIM + 255) / 256, 256>>>(wq, wk, wv, wo);

    cudaFuncSetAttribute(gemm_bf16x3<true>,
                         cudaFuncAttributeMaxDynamicSharedMemorySize, GS_TOTAL);
    cudaFuncSetAttribute(gemm_bf16x3<false>,
                         cudaFuncAttributeMaxDynamicSharedMemorySize, GS_TOTAL);
    dim3 gp(DIM / 64, BS / 128);   // (16, 32)
    gemm_bf16x3<true><<<gp, 256, GS_TOTAL>>>(tokh, tokl, wqh, wql, nullptr, qh, ql);
    gemm_bf16x3<true><<<gp, 256, GS_TOTAL>>>(tokh, tokl, wkh, wkl, nullptr, kh, kl);
    gemm_bf16x3<true><<<gp, 256, GS_TOTAL>>>(tokh, tokl, wvh, wvl, nullptr, vh, vl);

    cudaFuncSetAttribute(flash_attn_mma,
                         cudaFuncAttributeMaxDynamicSharedMemorySize, FA_TOTAL);
    flash_attn_mma<<<dim3(SEQ / 128, BATCH * HEADS), 256, FA_TOTAL>>>(
        qh, ql, kh, kl, vh, vl, aggh, aggl);

    gemm_bf16x3<false><<<gp, 256, GS_TOTAL>>>(aggh, aggl, woh, wol, out, nullptr, nullptr);
}

// round 5
// speedup vs baseline: 2.9899x; 1.3200x over previous
#include <cuda_runtime.h>
#include <cuda_bf16.h>
#include <cstdint>

#define BATCH 2
#define SEQ 2048
#define DIM 1024
#define HEADS 16
#define DHEAD 64
#define BS (BATCH*SEQ)   // 4096

// ---------------- scratch (device globals; no allocations allowed) ----------
__device__ __nv_bfloat16 g_tokh[BS*DIM], g_tokl[BS*DIM];
__device__ __nv_bfloat16 g_qh[BS*DIM], g_ql[BS*DIM];
__device__ __nv_bfloat16 g_kh[BS*DIM], g_kl[BS*DIM];
__device__ __nv_bfloat16 g_vh[BS*DIM], g_vl[BS*DIM];
__device__ __nv_bfloat16 g_aggh[BS*DIM], g_aggl[BS*DIM];
__device__ __nv_bfloat16 g_wqh[DIM*DIM], g_wql[DIM*DIM];
__device__ __nv_bfloat16 g_wkh[DIM*DIM], g_wkl[DIM*DIM];
__device__ __nv_bfloat16 g_wvh[DIM*DIM], g_wvl[DIM*DIM];
__device__ __nv_bfloat16 g_woh[DIM*DIM], g_wol[DIM*DIM];

// ---------------- helpers ----------------------------------------------------
__device__ __forceinline__ uint32_t smem_u32(const void* p) {
    uint32_t a;
    asm("{ .reg .u64 t; cvta.to.shared.u64 t, %1; cvt.u32.u64 %0, t; }"
        : "=r"(a) : "l"(p));
    return a;
}
#define SWZ128(o) ((o) ^ (((o) >> 3) & 0x70))

__device__ __forceinline__ void cp16(uint32_t saddr, const void* gptr) {
    asm volatile("cp.async.cg.shared.global [%0], [%1], 16;"
                 :: "r"(saddr), "l"(gptr));
}
#define CP_COMMIT() asm volatile("cp.async.commit_group;" ::: "memory")
#define CP_WAIT0()  asm volatile("cp.async.wait_group 0;" ::: "memory")

__device__ __forceinline__ void ldsm_x4(uint32_t* r, uint32_t addr) {
    asm volatile("ldmatrix.sync.aligned.m8n8.x4.shared.b16 {%0,%1,%2,%3}, [%4];"
                 : "=r"(r[0]), "=r"(r[1]), "=r"(r[2]), "=r"(r[3]) : "r"(addr));
}
__device__ __forceinline__ void ldsm_x2(uint32_t* r, uint32_t addr) {
    asm volatile("ldmatrix.sync.aligned.m8n8.x2.shared.b16 {%0,%1}, [%2];"
                 : "=r"(r[0]), "=r"(r[1]) : "r"(addr));
}
__device__ __forceinline__ void ldsm_x2t(uint32_t* r, uint32_t addr) {
    asm volatile("ldmatrix.sync.aligned.m8n8.x2.trans.shared.b16 {%0,%1}, [%2];"
                 : "=r"(r[0]), "=r"(r[1]) : "r"(addr));
}
__device__ __forceinline__ void mma_bf16(float* c, const uint32_t* a, const uint32_t* b) {
    asm volatile(
        "mma.sync.aligned.m16n8k16.row.col.f32.bf16.bf16.f32 "
        "{%0,%1,%2,%3}, {%4,%5,%6,%7}, {%8,%9}, {%0,%1,%2,%3};"
        : "+f"(c[0]), "+f"(c[1]), "+f"(c[2]), "+f"(c[3])
        : "r"(a[0]), "r"(a[1]), "r"(a[2]), "r"(a[3]), "r"(b[0]), "r"(b[1]));
}
__device__ __forceinline__ void bsplit(float v, __nv_bfloat16& h, __nv_bfloat16& l) {
    h = __float2bfloat16(v);
    l = __float2bfloat16(v - __bfloat162float(h));
}
__device__ __forceinline__ __nv_bfloat162 mk2(__nv_bfloat16 a, __nv_bfloat16 b) {
    __nv_bfloat162 t; t.x = a; t.y = b; return t;
}

// ---------------- split / pack kernels ---------------------------------------
__global__ void split_act(const float4* __restrict__ x,
                          __nv_bfloat16* __restrict__ hi,
                          __nv_bfloat16* __restrict__ lo, int n4) {
    int i = blockIdx.x * blockDim.x + threadIdx.x;
    if (i >= n4) return;
    float4 v = x[i];
    __nv_bfloat16 h0, l0, h1, l1, h2, l2, h3, l3;
    bsplit(v.x, h0, l0); bsplit(v.y, h1, l1);
    bsplit(v.z, h2, l2); bsplit(v.w, h3, l3);
    __nv_bfloat162* H = reinterpret_cast<__nv_bfloat162*>(hi);
    __nv_bfloat162* L = reinterpret_cast<__nv_bfloat162*>(lo);
    H[2 * i] = mk2(h0, h1);
    H[2 * i + 1] = mk2(h2, h3);
    L[2 * i] = mk2(l0, l1);
    L[2 * i + 1] = mk2(l2, l3);
}

__global__ void pack_w(const float* __restrict__ wq, const float* __restrict__ wk,
                       const float* __restrict__ wv, const float* __restrict__ wo) {
    int idx = blockIdx.x * blockDim.x + threadIdx.x;
    if (idx >= DIM * DIM) return;
    int n = idx >> 10;
    int k = idx & 1023;
    int h = n >> 6, e = n & 63;
    int src = (h * DIM + k) * DHEAD + e;
    bsplit(wq[src] * 0.125f, g_wqh[idx], g_wql[idx]);   // SCALE = 64^-0.5
    bsplit(wk[src], g_wkh[idx], g_wkl[idx]);
    bsplit(wv[src], g_wvh[idx], g_wvl[idx]);
    bsplit(wo[k * DIM + n], g_woh[idx], g_wol[idx]);
}

// ---------------- bf16x3 GEMM (HMMA + cp.async 2-stage) -----------------------
// C[M,N] = (Ah+Al)(Bh+Bl)^T, CTA 128x64, BK=64, 2-stage cp.async pipeline.
// Per stage: AH 16K | AL 16K | BH 8K | BL 8K = 48K. 2 stages = 96K.
#define ST_AL 16384
#define ST_BH 32768
#define ST_BL 40960
#define ST_SZ 49152
#define GS2_TOTAL (2*ST_SZ)

template <bool SPLIT>
__device__ __forceinline__ void gemm_body(
    const __nv_bfloat16* __restrict__ Ah, const __nv_bfloat16* __restrict__ Al,
    const __nv_bfloat16* __restrict__ Bh, const __nv_bfloat16* __restrict__ Bl,
    float* __restrict__ C, __nv_bfloat16* __restrict__ Ch,
    __nv_bfloat16* __restrict__ Cl, char* smem) {
    const uint32_t sb = smem_u32(smem);
    const int tid = threadIdx.x;
    const int lane = tid & 31;
    const int wid = tid >> 5;
    const int warp_m = wid & 3;
    const int warp_n = wid >> 2;
    const int row0 = blockIdx.y * 128;
    const int col0 = blockIdx.x * 64;

    const uint4* gA[2] = {reinterpret_cast<const uint4*>(Ah + (size_t)row0 * DIM),
                          reinterpret_cast<const uint4*>(Al + (size_t)row0 * DIM)};
    const uint4* gB[2] = {reinterpret_cast<const uint4*>(Bh + (size_t)col0 * DIM),
                          reinterpret_cast<const uint4*>(Bl + (size_t)col0 * DIM)};

    // per-thread load slots
    const int lrow = tid >> 3, lcol = tid & 7;   // 32 rows x 8 cols per 256-thr pass

    auto load_stage = [&](int cidx, int s) {
        const int k0u = cidx * 8;
        const uint32_t sbase = sb + s * ST_SZ;
#pragma unroll
        for (int m = 0; m < 2; m++) {
#pragma unroll
            for (int r4 = 0; r4 < 4; r4++) {
                int row = lrow + r4 * 32;
                uint32_t off = SWZ128(row * 128 + lcol * 16);
                cp16(sbase + (m ? ST_AL : 0) + off, gA[m] + row * 128 + k0u + lcol);
            }
#pragma unroll
            for (int r4 = 0; r4 < 2; r4++) {
                int row = lrow + r4 * 32;
                uint32_t off = SWZ128(row * 128 + lcol * 16);
                cp16(sbase + (m ? ST_BL : ST_BH) + off, gB[m] + row * 128 + k0u + lcol);
            }
        }
        CP_COMMIT();
    };

    int amask[2], abase[2];
#pragma unroll
    for (int i = 0; i < 2; i++) {
        int r = warp_m * 32 + i * 16 + (lane & 15);
        amask[i] = (r & 7) << 4;
        abase[i] = r * 128 + ((lane >> 4) & 1) * 16;
    }
    const int brow = warp_n * 32 + (lane & 7);
    const int bmaskbase = ((lane & 15) >> 3) * 16;

    float acc[2][4][4] = {};

    load_stage(0, 0);
    CP_WAIT0();
    __syncthreads();

    for (int c = 0; c < 16; c++) {
        if (c < 15) load_stage(c + 1, (c + 1) & 1);
        const uint32_t sbase = sb + (c & 1) * ST_SZ;
#pragma unroll
        for (int ks = 0; ks < 4; ks++) {
            uint32_t ah[2][4], al[2][4], bh[4][2], bl[4][2];
#pragma unroll
            for (int i = 0; i < 2; i++) {
                uint32_t offA = (abase[i] + ks * 32) ^ amask[i];
                ldsm_x4(ah[i], sbase + offA);
                ldsm_x4(al[i], sbase + ST_AL + offA);
            }
#pragma unroll
            for (int j = 0; j < 4; j++) {
                int r = brow + j * 8;
                uint32_t offB = (r * 128 + bmaskbase + ks * 32) ^ ((r & 7) << 4);
                ldsm_x2(bh[j], sbase + ST_BH + offB);
                ldsm_x2(bl[j], sbase + ST_BL + offB);
            }
#pragma unroll
            for (int i = 0; i < 2; i++)
#pragma unroll
                for (int j = 0; j < 4; j++) {
                    mma_bf16(acc[i][j], ah[i], bh[j]);
                    mma_bf16(acc[i][j], ah[i], bl[j]);
                    mma_bf16(acc[i][j], al[i], bh[j]);
                }
        }
        if (c < 15) {
            CP_WAIT0();
            __syncthreads();
        }
    }

    const int fr = lane >> 2, fc = (lane & 3) * 2;
#pragma unroll
    for (int i = 0; i < 2; i++) {
        int rbase = row0 + warp_m * 32 + i * 16 + fr;
#pragma unroll
        for (int j = 0; j < 4; j++) {
            int col = col0 + warp_n * 32 + j * 8 + fc;
            if (SPLIT) {
                __nv_bfloat16 h0, l0, h1, l1;
                bsplit(acc[i][j][0], h0, l0); bsplit(acc[i][j][1], h1, l1);
                *reinterpret_cast<__nv_bfloat162*>(&Ch[(size_t)rbase * DIM + col]) = mk2(h0, h1);
                *reinterpret_cast<__nv_bfloat162*>(&Cl[(size_t)rbase * DIM + col]) = mk2(l0, l1);
                bsplit(acc[i][j][2], h0, l0); bsplit(acc[i][j][3], h1, l1);
                *reinterpret_cast<__nv_bfloat162*>(&Ch[(size_t)(rbase + 8) * DIM + col]) = mk2(h0, h1);
                *reinterpret_cast<__nv_bfloat162*>(&Cl[(size_t)(rbase + 8) * DIM + col]) = mk2(l0, l1);
            } else {
                *reinterpret_cast<float2*>(&C[(size_t)rbase * DIM + col]) =
                    make_float2(acc[i][j][0], acc[i][j][1]);
                *reinterpret_cast<float2*>(&C[(size_t)(rbase + 8) * DIM + col]) =
                    make_float2(acc[i][j][2], acc[i][j][3]);
            }
        }
    }
}

struct QKVArgs {
    const __nv_bfloat16* bh[3];
    const __nv_bfloat16* bl[3];
    __nv_bfloat16* ch[3];
    __nv_bfloat16* cl[3];
};

__global__ __launch_bounds__(256, 2) void gemm_qkv(
    const __nv_bfloat16* __restrict__ Ah, const __nv_bfloat16* __restrict__ Al,
    QKVArgs args) {
    extern __shared__ char smem[];
    const int z = blockIdx.z;
    gemm_body<true>(Ah, Al, args.bh[z], args.bl[z], nullptr,
                    args.ch[z], args.cl[z], smem);
}

__global__ __launch_bounds__(256, 2) void gemm_wo(
    const __nv_bfloat16* __restrict__ Ah, const __nv_bfloat16* __restrict__ Al,
    const __nv_bfloat16* __restrict__ Bh, const __nv_bfloat16* __restrict__ Bl,
    float* __restrict__ C) {
    extern __shared__ char smem[];
    gemm_body<false>(Ah, Al, Bh, Bl, C, nullptr, nullptr, smem);
}

// ---------------- flash attention (HMMA + cp.async double-buffered KV) -------
// smem: QH 0 (16K) | QL 16K | KV stage0 @32K (KH,KL,VH,VL 8K each) |
//       KV stage1 @64K | PH 96K (16K) | PL 112K | state @128K
#define FA_QL 16384
#define FA_KV0 32768
#define FA_KVS 32768
#define FA_KL_O 8192
#define FA_VH_O 16384
#define FA_VL_O 24576
#define FA_PH 98304
#define FA_PL 114688
#define FA_MR 131072
#define FA_LR (131072+512)
#define FA_RM (131072+1024)
#define FA_RL (131072+2048)
#define FA_TOTAL (131072+3072)

__global__ __launch_bounds__(256) void flash_attn_mma(
    const __nv_bfloat16* __restrict__ Qh, const __nv_bfloat16* __restrict__ Ql,
    const __nv_bfloat16* __restrict__ Kh, const __nv_bfloat16* __restrict__ Kl,
    const __nv_bfloat16* __restrict__ Vh, const __nv_bfloat16* __restrict__ Vl,
    __nv_bfloat16* __restrict__ Oh, __nv_bfloat16* __restrict__ Ol) {
    extern __shared__ char smem[];
    const uint32_t sb = smem_u32(smem);
    const int tid = threadIdx.x, lane = tid & 31, wid = tid >> 5;
    const int wm = wid & 3, wn = wid >> 2;
    const int qt = blockIdx.x, bh = blockIdx.y;
    const int b = bh >> 4, h = bh & 15;
    const size_t base = ((size_t)(b * SEQ) * HEADS + h) * DHEAD;
    const uint4* Qhp = reinterpret_cast<const uint4*>(Qh + base);
    const uint4* Qlp = reinterpret_cast<const uint4*>(Ql + base);
    const uint4* Khp = reinterpret_cast<const uint4*>(Kh + base);
    const uint4* Klp = reinterpret_cast<const uint4*>(Kl + base);
    const uint4* Vhp = reinterpret_cast<const uint4*>(Vh + base);
    const uint4* Vlp = reinterpret_cast<const uint4*>(Vl + base);
    float* mrow = reinterpret_cast<float*>(smem + FA_MR);
    float* lrow = reinterpret_cast<float*>(smem + FA_LR);
    float* redm = reinterpret_cast<float*>(smem + FA_RM);
    float* redl = reinterpret_cast<float*>(smem + FA_RL);

    const int lrw = tid >> 3, lcl = tid & 7;

    auto load_kv = [&](int jt, int s) {
        const uint32_t kvb = sb + FA_KV0 + s * FA_KVS;
#pragma unroll
        for (int r4 = 0; r4 < 2; r4++) {
            int row = lrw + r4 * 32;
            uint32_t off = SWZ128(row * 128 + lcl * 16);
            int g = (jt * 64 + row) * 128 + lcl;
            cp16(kvb + off, Khp + g);
            cp16(kvb + FA_KL_O + off, Klp + g);
            cp16(kvb + FA_VH_O + off, Vhp + g);
            cp16(kvb + FA_VL_O + off, Vlp + g);
        }
        CP_COMMIT();
    };

    // prefetch KV(0), then load Q
    load_kv(0, 0);
#pragma unroll
    for (int r4 = 0; r4 < 4; r4++) {
        int row = lrw + r4 * 32;
        uint32_t off = SWZ128(row * 128 + lcl * 16);
        int g = (qt * 128 + row) * 128 + lcl;
        *reinterpret_cast<uint4*>(smem + off) = Qhp[g];
        *reinterpret_cast<uint4*>(smem + FA_QL + off) = Qlp[g];
    }
    if (tid < 128) { mrow[tid] = -1e30f; lrow[tid] = 0.f; }

    float o[2][4][4] = {};
    const int fr = lane >> 2, fc = (lane & 3) * 2;
    const int aRow = lane & 15, aCol = (lane >> 4) * 16;
    const int l16 = lane & 15;
    const int bkRow = l16 & 7, bkHalf = (l16 >> 3) * 16;
    CP_WAIT0();
    __syncthreads();

    for (int jt = 0; jt < SEQ / 64; jt++) {
        const uint32_t kvb = sb + FA_KV0 + (jt & 1) * FA_KVS;
        if (jt + 1 < SEQ / 64) load_kv(jt + 1, (jt + 1) & 1);

        // S = Q K^T (x3)
        float s[2][4][4] = {};
#pragma unroll
        for (int ks = 0; ks < 4; ks++) {
            uint32_t ah[2][4], al[2][4], bhr[4][2], blr[4][2];
#pragma unroll
            for (int i = 0; i < 2; i++) {
                uint32_t off = SWZ128((wm * 32 + i * 16 + aRow) * 128 + ks * 32 + aCol);
                ldsm_x4(ah[i], sb + off);
                ldsm_x4(al[i], sb + FA_QL + off);
            }
#pragma unroll
            for (int j = 0; j < 4; j++) {
                uint32_t off = SWZ128((wn * 32 + j * 8 + bkRow) * 128 + ks * 32 + bkHalf);
                ldsm_x2(bhr[j], kvb + off);
                ldsm_x2(blr[j], kvb + FA_KL_O + off);
            }
#pragma unroll
            for (int i = 0; i < 2; i++)
#pragma unroll
                for (int j = 0; j < 4; j++) {
                    mma_bf16(s[i][j], ah[i], bhr[j]);
                    mma_bf16(s[i][j], ah[i], blr[j]);
                    mma_bf16(s[i][j], al[i], bhr[j]);
                }
        }

        // softmax phase 1: per-warp row max -> redm
#pragma unroll
        for (int i = 0; i < 2; i++)
#pragma unroll
            for (int hf = 0; hf < 2; hf++) {
                float v = s[i][0][hf * 2];
#pragma unroll
                for (int j = 0; j < 4; j++) {
                    v = fmaxf(v, s[i][j][hf * 2]);
                    v = fmaxf(v, s[i][j][hf * 2 + 1]);
                }
                v = fmaxf(v, __shfl_xor_sync(0xffffffffu, v, 1));
                v = fmaxf(v, __shfl_xor_sync(0xffffffffu, v, 2));
                if ((lane & 3) == 0)
                    redm[wn * 128 + wm * 32 + i * 16 + hf * 8 + fr] = v;
            }
        __syncthreads();

        // phase 2: alpha, exp, write P, partial row sums
        float alpha[2][2], mnew[2][2], rsum[2][2];
#pragma unroll
        for (int i = 0; i < 2; i++)
#pragma unroll
            for (int hf = 0; hf < 2; hf++) {
                int r = wm * 32 + i * 16 + hf * 8 + fr;
                float mo = mrow[r];
                float mn = fmaxf(mo, fmaxf(redm[r], redm[128 + r]));
                mnew[i][hf] = mn;
                alpha[i][hf] = __expf(mo - mn);
                rsum[i][hf] = 0.f;
            }
#pragma unroll
        for (int i = 0; i < 2; i++)
#pragma unroll
            for (int j = 0; j < 4; j++)
#pragma unroll
                for (int hf = 0; hf < 2; hf++) {
                    float p0 = __expf(s[i][j][hf * 2] - mnew[i][hf]);
                    float p1 = __expf(s[i][j][hf * 2 + 1] - mnew[i][hf]);
                    rsum[i][hf] += p0 + p1;
                    __nv_bfloat16 h0, l0, h1, l1;
                    bsplit(p0, h0, l0); bsplit(p1, h1, l1);
                    int r = wm * 32 + i * 16 + hf * 8 + fr;
                    uint32_t off = SWZ128(r * 128 + (wn * 32 + j * 8 + fc) * 2);
                    *reinterpret_cast<__nv_bfloat162*>(smem + FA_PH + off) = mk2(h0, h1);
                    *reinterpret_cast<__nv_bfloat162*>(smem + FA_PL + off) = mk2(l0, l1);
                }
#pragma unroll
        for (int i = 0; i < 2; i++)
#pragma unroll
            for (int hf = 0; hf < 2; hf++) {
                float v = rsum[i][hf];
                v += __shfl_xor_sync(0xffffffffu, v, 1);
                v += __shfl_xor_sync(0xffffffffu, v, 2);
                if ((lane & 3) == 0)
                    redl[wn * 128 + wm * 32 + i * 16 + hf * 8 + fr] = v;
            }
        __syncthreads();

        // state update
        if (tid < 128) {
            float mo = mrow[tid];
            float mn = fmaxf(mo, fmaxf(redm[tid], redm[128 + tid]));
            lrow[tid] = lrow[tid] * __expf(mo - mn) + redl[tid] + redl[128 + tid];
            mrow[tid] = mn;
        }
        // rescale O
#pragma unroll
        for (int i = 0; i < 2; i++)
#pragma unroll
            for (int j = 0; j < 4; j++)
#pragma unroll
                for (int hf = 0; hf < 2; hf++) {
                    o[i][j][hf * 2] *= alpha[i][hf];
                    o[i][j][hf * 2 + 1] *= alpha[i][hf];
                }
        // O += P V (x3)
#pragma unroll
        for (int ks = 0; ks < 4; ks++) {
            uint32_t ph[2][4], pl[2][4], vh[4][2], vl[4][2];
#pragma unroll
            for (int i = 0; i < 2; i++) {
                uint32_t off = SWZ128((wm * 32 + i * 16 + aRow) * 128 + ks * 32 + aCol);
                ldsm_x4(ph[i], sb + FA_PH + off);
                ldsm_x4(pl[i], sb + FA_PL + off);
            }
#pragma unroll
            for (int j = 0; j < 4; j++) {
                uint32_t off = SWZ128((ks * 16 + l16) * 128 + (wn * 32 + j * 8) * 2);
                ldsm_x2t(vh[j], kvb + FA_VH_O + off);
                ldsm_x2t(vl[j], kvb + FA_VL_O + off);
            }
#pragma unroll
            for (int i = 0; i < 2; i++)
#pragma unroll
                for (int j = 0; j < 4; j++) {
                    mma_bf16(o[i][j], ph[i], vh[j]);
                    mma_bf16(o[i][j], ph[i], vl[j]);
                    mma_bf16(o[i][j], pl[i], vh[j]);
                }
        }
        if (jt + 1 < SEQ / 64) CP_WAIT0();
        __syncthreads();
    }

    // epilogue: normalize, split, store
#pragma unroll
    for (int i = 0; i < 2; i++)
#pragma unroll
        for (int hf = 0; hf < 2; hf++) {
            int r = wm * 32 + i * 16 + hf * 8 + fr;
            float inv = 1.f / lrow[r];
#pragma unroll
            for (int j = 0; j < 4; j++) {
                float v0 = o[i][j][hf * 2] * inv;
                float v1 = o[i][j][hf * 2 + 1] * inv;
                __nv_bfloat16 h0, l0, h1, l1;
                bsplit(v0, h0, l0); bsplit(v1, h1, l1);
                size_t off = (size_t)(qt * 128 + r) * 1024 + wn * 32 + j * 8 + fc;
                *reinterpret_cast<__nv_bfloat162*>(Oh + base + off) = mk2(h0, h1);
                *reinterpret_cast<__nv_bfloat162*>(Ol + base + off) = mk2(l0, l1);
            }
        }
}

// ---------------- launch ------------------------------------------------------
extern "C" void kernel_launch(void* const* d_in, const int* in_sizes, int n_in,
                              void* d_out, int out_size) {
    const float* tokens = (const float*)d_in[0];
    const float* wq = (const float*)d_in[1];
    const float* wk = (const float*)d_in[2];
    const float* wv = (const float*)d_in[3];
    const float* wo = (const float*)d_in[4];
    float* out = (float*)d_out;

    __nv_bfloat16 *tokh, *tokl, *qh, *ql, *kh, *kl, *vh, *vl, *aggh, *aggl;
    __nv_bfloat16 *wqh, *wql, *wkh, *wkl, *wvh, *wvl, *woh, *wol;
    cudaGetSymbolAddress((void**)&tokh, g_tokh);
    cudaGetSymbolAddress((void**)&tokl, g_tokl);
    cudaGetSymbolAddress((void**)&qh, g_qh);
    cudaGetSymbolAddress((void**)&ql, g_ql);
    cudaGetSymbolAddress((void**)&kh, g_kh);
    cudaGetSymbolAddress((void**)&kl, g_kl);
    cudaGetSymbolAddress((void**)&vh, g_vh);
    cudaGetSymbolAddress((void**)&vl, g_vl);
    cudaGetSymbolAddress((void**)&aggh, g_aggh);
    cudaGetSymbolAddress((void**)&aggl, g_aggl);
    cudaGetSymbolAddress((void**)&wqh, g_wqh);
    cudaGetSymbolAddress((void**)&wql, g_wql);
    cudaGetSymbolAddress((void**)&wkh, g_wkh);
    cudaGetSymbolAddress((void**)&wkl, g_wkl);
    cudaGetSymbolAddress((void**)&wvh, g_wvh);
    cudaGetSymbolAddress((void**)&wvl, g_wvl);
    cudaGetSymbolAddress((void**)&woh, g_woh);
    cudaGetSymbolAddress((void**)&wol, g_wol);

    split_act<<<(BS * DIM / 4 + 255) / 256, 256>>>(
        (const float4*)tokens, tokh, tokl, BS * DIM / 4);
    pack_w<<<(DIM * DIM + 255) / 256, 256>>>(wq, wk, wv, wo);

    cudaFuncSetAttribute(gemm_qkv, cudaFuncAttributeMaxDynamicSharedMemorySize,
                         GS2_TOTAL);
    cudaFuncSetAttribute(gemm_wo, cudaFuncAttributeMaxDynamicSharedMemorySize,
                         GS2_TOTAL);

    QKVArgs args;
    args.bh[0] = wqh; args.bl[0] = wql; args.ch[0] = qh; args.cl[0] = ql;
    args.bh[1] = wkh; args.bl[1] = wkl; args.ch[1] = kh; args.cl[1] = kl;
    args.bh[2] = wvh; args.bl[2] = wvl; args.ch[2] = vh; args.cl[2] = vl;

    dim3 gqkv(DIM / 64, BS / 128, 3);   // (16, 32, 3)
    gemm_qkv<<<gqkv, 256, GS2_TOTAL>>>(tokh, tokl, args);

    cudaFuncSetAttribute(flash_attn_mma,
                         cudaFuncAttributeMaxDynamicSharedMemorySize, FA_TOTAL);
    flash_attn_mma<<<dim3(SEQ / 128, BATCH * HEADS), 256, FA_TOTAL>>>(
        qh, ql, kh, kl, vh, vl, aggh, aggl);

    dim3 gp(DIM / 64, BS / 128);   // (16, 32)
    gemm_wo<<<gp, 256, GS2_TOTAL>>>(aggh, aggl, woh, wol, out);
}

// round 6
// speedup vs baseline: 3.2366x; 1.0825x over previous
#include <cuda_runtime.h>
#include <cuda_bf16.h>
#include <cstdint>

#define BATCH 2
#define SEQ 2048
#define DIM 1024
#define HEADS 16
#define DHEAD 64
#define BS (BATCH*SEQ)   // 4096

// ---------------- scratch (device globals; no allocations allowed) ----------
__device__ __nv_bfloat16 g_tokh[BS*DIM], g_tokl[BS*DIM];
__device__ __nv_bfloat16 g_qh[BS*DIM], g_ql[BS*DIM];
__device__ __nv_bfloat16 g_kh[BS*DIM], g_kl[BS*DIM];
__device__ __nv_bfloat16 g_vh[BS*DIM], g_vl[BS*DIM];
__device__ __nv_bfloat16 g_aggh[BS*DIM], g_aggl[BS*DIM];
__device__ __nv_bfloat16 g_wqh[DIM*DIM], g_wql[DIM*DIM];
__device__ __nv_bfloat16 g_wkh[DIM*DIM], g_wkl[DIM*DIM];
__device__ __nv_bfloat16 g_wvh[DIM*DIM], g_wvl[DIM*DIM];
__device__ __nv_bfloat16 g_woh[DIM*DIM], g_wol[DIM*DIM];

// ---------------- helpers ----------------------------------------------------
__device__ __forceinline__ uint32_t smem_u32(const void* p) {
    uint32_t a;
    asm("{ .reg .u64 t; cvta.to.shared.u64 t, %1; cvt.u32.u64 %0, t; }"
        : "=r"(a) : "l"(p));
    return a;
}
#define SWZ128(o) ((o) ^ (((o) >> 3) & 0x70))

__device__ __forceinline__ void cp16(uint32_t saddr, const void* gptr) {
    asm volatile("cp.async.cg.shared.global [%0], [%1], 16;"
                 :: "r"(saddr), "l"(gptr));
}
#define CP_COMMIT() asm volatile("cp.async.commit_group;" ::: "memory")
#define CP_WAIT0()  asm volatile("cp.async.wait_group 0;" ::: "memory")

__device__ __forceinline__ void ldsm_x4(uint32_t* r, uint32_t addr) {
    asm volatile("ldmatrix.sync.aligned.m8n8.x4.shared.b16 {%0,%1,%2,%3}, [%4];"
                 : "=r"(r[0]), "=r"(r[1]), "=r"(r[2]), "=r"(r[3]) : "r"(addr));
}
__device__ __forceinline__ void ldsm_x2(uint32_t* r, uint32_t addr) {
    asm volatile("ldmatrix.sync.aligned.m8n8.x2.shared.b16 {%0,%1}, [%2];"
                 : "=r"(r[0]), "=r"(r[1]) : "r"(addr));
}
__device__ __forceinline__ void ldsm_x4t(uint32_t* r, uint32_t addr) {
    asm volatile("ldmatrix.sync.aligned.m8n8.x4.trans.shared.b16 {%0,%1,%2,%3}, [%4];"
                 : "=r"(r[0]), "=r"(r[1]), "=r"(r[2]), "=r"(r[3]) : "r"(addr));
}
__device__ __forceinline__ void mma_bf16(float* c, const uint32_t* a, const uint32_t* b) {
    asm volatile(
        "mma.sync.aligned.m16n8k16.row.col.f32.bf16.bf16.f32 "
        "{%0,%1,%2,%3}, {%4,%5,%6,%7}, {%8,%9}, {%0,%1,%2,%3};"
        : "+f"(c[0]), "+f"(c[1]), "+f"(c[2]), "+f"(c[3])
        : "r"(a[0]), "r"(a[1]), "r"(a[2]), "r"(a[3]), "r"(b[0]), "r"(b[1]));
}
__device__ __forceinline__ void bsplit(float v, __nv_bfloat16& h, __nv_bfloat16& l) {
    h = __float2bfloat16(v);
    l = __float2bfloat16(v - __bfloat162float(h));
}
__device__ __forceinline__ __nv_bfloat162 mk2(__nv_bfloat16 a, __nv_bfloat16 b) {
    __nv_bfloat162 t; t.x = a; t.y = b; return t;
}
__device__ __forceinline__ uint32_t pack_bf2(float a, float b) {
    __nv_bfloat162 t; t.x = __float2bfloat16(a); t.y = __float2bfloat16(b);
    return *reinterpret_cast<uint32_t*>(&t);
}

// ---------------- split / pack kernels ---------------------------------------
__global__ void split_act(const float4* __restrict__ x,
                          __nv_bfloat16* __restrict__ hi,
                          __nv_bfloat16* __restrict__ lo, int n4) {
    int i = blockIdx.x * blockDim.x + threadIdx.x;
    if (i >= n4) return;
    float4 v = x[i];
    __nv_bfloat16 h0, l0, h1, l1, h2, l2, h3, l3;
    bsplit(v.x, h0, l0); bsplit(v.y, h1, l1);
    bsplit(v.z, h2, l2); bsplit(v.w, h3, l3);
    __nv_bfloat162* H = reinterpret_cast<__nv_bfloat162*>(hi);
    __nv_bfloat162* L = reinterpret_cast<__nv_bfloat162*>(lo);
    H[2 * i] = mk2(h0, h1);
    H[2 * i + 1] = mk2(h2, h3);
    L[2 * i] = mk2(l0, l1);
    L[2 * i + 1] = mk2(l2, l3);
}

__global__ void pack_w(const float* __restrict__ wq, const float* __restrict__ wk,
                       const float* __restrict__ wv, const float* __restrict__ wo) {
    int idx = blockIdx.x * blockDim.x + threadIdx.x;
    if (idx >= DIM * DIM) return;
    int n = idx >> 10;
    int k = idx & 1023;
    int h = n >> 6, e = n & 63;
    int src = (h * DIM + k) * DHEAD + e;
    bsplit(wq[src] * 0.125f, g_wqh[idx], g_wql[idx]);   // SCALE = 64^-0.5
    bsplit(wk[src], g_wkh[idx], g_wkl[idx]);
    bsplit(wv[src], g_wvh[idx], g_wvl[idx]);
    bsplit(wo[k * DIM + n], g_woh[idx], g_wol[idx]);
}

// ---------------- bf16x3 GEMM (HMMA + cp.async 2-stage) -----------------------
#define ST_AL 16384
#define ST_BH 32768
#define ST_BL 40960
#define ST_SZ 49152
#define GS2_TOTAL (2*ST_SZ)

template <bool SPLIT>
__device__ __forceinline__ void gemm_body(
    const __nv_bfloat16* __restrict__ Ah, const __nv_bfloat16* __restrict__ Al,
    const __nv_bfloat16* __restrict__ Bh, const __nv_bfloat16* __restrict__ Bl,
    float* __restrict__ C, __nv_bfloat16* __restrict__ Ch,
    __nv_bfloat16* __restrict__ Cl, char* smem) {
    const uint32_t sb = smem_u32(smem);
    const int tid = threadIdx.x;
    const int lane = tid & 31;
    const int wid = tid >> 5;
    const int warp_m = wid & 3;
    const int warp_n = wid >> 2;
    const int row0 = blockIdx.y * 128;
    const int col0 = blockIdx.x * 64;

    const uint4* gA[2] = {reinterpret_cast<const uint4*>(Ah + (size_t)row0 * DIM),
                          reinterpret_cast<const uint4*>(Al + (size_t)row0 * DIM)};
    const uint4* gB[2] = {reinterpret_cast<const uint4*>(Bh + (size_t)col0 * DIM),
                          reinterpret_cast<const uint4*>(Bl + (size_t)col0 * DIM)};

    const int lrow = tid >> 3, lcol = tid & 7;

    auto load_stage = [&](int cidx, int s) {
        const int k0u = cidx * 8;
        const uint32_t sbase = sb + s * ST_SZ;
#pragma unroll
        for (int m = 0; m < 2; m++) {
#pragma unroll
            for (int r4 = 0; r4 < 4; r4++) {
                int row = lrow + r4 * 32;
                uint32_t off = SWZ128(row * 128 + lcol * 16);
                cp16(sbase + (m ? ST_AL : 0) + off, gA[m] + row * 128 + k0u + lcol);
            }
#pragma unroll
            for (int r4 = 0; r4 < 2; r4++) {
                int row = lrow + r4 * 32;
                uint32_t off = SWZ128(row * 128 + lcol * 16);
                cp16(sbase + (m ? ST_BL : ST_BH) + off, gB[m] + row * 128 + k0u + lcol);
            }
        }
        CP_COMMIT();
    };

    int amask[2], abase[2];
#pragma unroll
    for (int i = 0; i < 2; i++) {
        int r = warp_m * 32 + i * 16 + (lane & 15);
        amask[i] = (r & 7) << 4;
        abase[i] = r * 128 + ((lane >> 4) & 1) * 16;
    }
    const int brow = warp_n * 32 + (lane & 7);
    const int bmaskbase = ((lane & 15) >> 3) * 16;

    float acc[2][4][4] = {};

    load_stage(0, 0);
    CP_WAIT0();
    __syncthreads();

    for (int c = 0; c < 16; c++) {
        if (c < 15) load_stage(c + 1, (c + 1) & 1);
        const uint32_t sbase = sb + (c & 1) * ST_SZ;
#pragma unroll
        for (int ks = 0; ks < 4; ks++) {
            uint32_t ah[2][4], al[2][4], bh[4][2], bl[4][2];
#pragma unroll
            for (int i = 0; i < 2; i++) {
                uint32_t offA = (abase[i] + ks * 32) ^ amask[i];
                ldsm_x4(ah[i], sbase + offA);
                ldsm_x4(al[i], sbase + ST_AL + offA);
            }
#pragma unroll
            for (int j = 0; j < 4; j++) {
                int r = brow + j * 8;
                uint32_t offB = (r * 128 + bmaskbase + ks * 32) ^ ((r & 7) << 4);
                ldsm_x2(bh[j], sbase + ST_BH + offB);
                ldsm_x2(bl[j], sbase + ST_BL + offB);
            }
#pragma unroll
            for (int i = 0; i < 2; i++)
#pragma unroll
                for (int j = 0; j < 4; j++) {
                    mma_bf16(acc[i][j], ah[i], bh[j]);
                    mma_bf16(acc[i][j], ah[i], bl[j]);
                    mma_bf16(acc[i][j], al[i], bh[j]);
                }
        }
        if (c < 15) {
            CP_WAIT0();
            __syncthreads();
        }
    }

    const int fr = lane >> 2, fc = (lane & 3) * 2;
#pragma unroll
    for (int i = 0; i < 2; i++) {
        int rbase = row0 + warp_m * 32 + i * 16 + fr;
#pragma unroll
        for (int j = 0; j < 4; j++) {
            int col = col0 + warp_n * 32 + j * 8 + fc;
            if (SPLIT) {
                __nv_bfloat16 h0, l0, h1, l1;
                bsplit(acc[i][j][0], h0, l0); bsplit(acc[i][j][1], h1, l1);
                *reinterpret_cast<__nv_bfloat162*>(&Ch[(size_t)rbase * DIM + col]) = mk2(h0, h1);
                *reinterpret_cast<__nv_bfloat162*>(&Cl[(size_t)rbase * DIM + col]) = mk2(l0, l1);
                bsplit(acc[i][j][2], h0, l0); bsplit(acc[i][j][3], h1, l1);
                *reinterpret_cast<__nv_bfloat162*>(&Ch[(size_t)(rbase + 8) * DIM + col]) = mk2(h0, h1);
                *reinterpret_cast<__nv_bfloat162*>(&Cl[(size_t)(rbase + 8) * DIM + col]) = mk2(l0, l1);
            } else {
                *reinterpret_cast<float2*>(&C[(size_t)rbase * DIM + col]) =
                    make_float2(acc[i][j][0], acc[i][j][1]);
                *reinterpret_cast<float2*>(&C[(size_t)(rbase + 8) * DIM + col]) =
                    make_float2(acc[i][j][2], acc[i][j][3]);
            }
        }
    }
}

struct QKVArgs {
    const __nv_bfloat16* bh[3];
    const __nv_bfloat16* bl[3];
    __nv_bfloat16* ch[3];
    __nv_bfloat16* cl[3];
};

__global__ __launch_bounds__(256, 2) void gemm_qkv(
    const __nv_bfloat16* __restrict__ Ah, const __nv_bfloat16* __restrict__ Al,
    QKVArgs args) {
    extern __shared__ char smem[];
    const int z = blockIdx.z;
    gemm_body<true>(Ah, Al, args.bh[z], args.bl[z], nullptr,
                    args.ch[z], args.cl[z], smem);
}

__global__ __launch_bounds__(256, 2) void gemm_wo(
    const __nv_bfloat16* __restrict__ Ah, const __nv_bfloat16* __restrict__ Al,
    const __nv_bfloat16* __restrict__ Bh, const __nv_bfloat16* __restrict__ Bl,
    float* __restrict__ C) {
    extern __shared__ char smem[];
    gemm_body<false>(Ah, Al, Bh, Bl, C, nullptr, nullptr, smem);
}

// ---------------- flash attention (FA2-style, register-resident P) ----------
// 8 warps x 16 query rows each; each warp spans full N=64 KV width.
// smem: QH 0 (16K) | QL 16K | KV stage0 @32K (KH,KL,VH,VL 8K each) | KV stage1 @64K
#define FA_QL 16384
#define FA_KV0 32768
#define FA_KVS 32768
#define FA_KL_O 8192
#define FA_VH_O 16384
#define FA_VL_O 24576
#define FA_TOTAL 98304

__global__ __launch_bounds__(256, 2) void flash_attn_mma(
    const __nv_bfloat16* __restrict__ Qh, const __nv_bfloat16* __restrict__ Ql,
    const __nv_bfloat16* __restrict__ Kh, const __nv_bfloat16* __restrict__ Kl,
    const __nv_bfloat16* __restrict__ Vh, const __nv_bfloat16* __restrict__ Vl,
    __nv_bfloat16* __restrict__ Oh, __nv_bfloat16* __restrict__ Ol) {
    extern __shared__ char smem[];
    const uint32_t sb = smem_u32(smem);
    const int tid = threadIdx.x, lane = tid & 31, wid = tid >> 5;
    const int qt = blockIdx.x, bhid = blockIdx.y;
    const int b = bhid >> 4, h = bhid & 15;
    const size_t base = ((size_t)(b * SEQ) * HEADS + h) * DHEAD;
    const uint4* Qhp = reinterpret_cast<const uint4*>(Qh + base);
    const uint4* Qlp = reinterpret_cast<const uint4*>(Ql + base);
    const uint4* Khp = reinterpret_cast<const uint4*>(Kh + base);
    const uint4* Klp = reinterpret_cast<const uint4*>(Kl + base);
    const uint4* Vhp = reinterpret_cast<const uint4*>(Vh + base);
    const uint4* Vlp = reinterpret_cast<const uint4*>(Vl + base);

    const int lrw = tid >> 3, lcl = tid & 7;

    auto load_kv = [&](int jt, int s) {
        const uint32_t kvb = sb + FA_KV0 + s * FA_KVS;
#pragma unroll
        for (int r4 = 0; r4 < 2; r4++) {
            int row = lrw + r4 * 32;
            uint32_t off = SWZ128(row * 128 + lcl * 16);
            int g = (jt * 64 + row) * 128 + lcl;
            cp16(kvb + off, Khp + g);
            cp16(kvb + FA_KL_O + off, Klp + g);
            cp16(kvb + FA_VH_O + off, Vhp + g);
            cp16(kvb + FA_VL_O + off, Vlp + g);
        }
        CP_COMMIT();
    };

    load_kv(0, 0);
#pragma unroll
    for (int r4 = 0; r4 < 4; r4++) {
        int row = lrw + r4 * 32;
        uint32_t off = SWZ128(row * 128 + lcl * 16);
        int g = (qt * 128 + row) * 128 + lcl;
        *reinterpret_cast<uint4*>(smem + off) = Qhp[g];
        *reinterpret_cast<uint4*>(smem + FA_QL + off) = Qlp[g];
    }

    float m0 = -1e30f, m1 = -1e30f, l0 = 0.f, l1 = 0.f;
    float o[8][4] = {};
    const int fr = lane >> 2, fc = (lane & 3) * 2;
    const int qrow = wid * 16;
    const int aRow = lane & 15, aCol = (lane >> 4) * 16;       // Q A-frag
    const int kRow = ((lane >> 4) & 1) * 8 + (lane & 7);       // K B-frag x4
    const int kHalf = ((lane >> 3) & 1) * 16;
    const int vRow = lane & 15;                                 // V B-frag x4t
    const int vColOff = ((lane >> 4) & 1) * 8;

    CP_WAIT0();
    __syncthreads();

    for (int jt = 0; jt < SEQ / 64; jt++) {
        const uint32_t kvb = sb + FA_KV0 + (jt & 1) * FA_KVS;
        if (jt + 1 < SEQ / 64) load_kv(jt + 1, (jt + 1) & 1);

        // ---- S = Q K^T (bf16x3) : 8 n-tiles of n8, K = 64 ----
        float s[8][4] = {};
#pragma unroll
        for (int ks = 0; ks < 4; ks++) {
            uint32_t ah[4], al[4];
            uint32_t offA = SWZ128((qrow + aRow) * 128 + ks * 32 + aCol);
            ldsm_x4(ah, sb + offA);
            ldsm_x4(al, sb + FA_QL + offA);
#pragma unroll
            for (int jj = 0; jj < 4; jj++) {
                uint32_t kh4[4], kl4[4];
                uint32_t offB = SWZ128((jj * 16 + kRow) * 128 + ks * 32 + kHalf);
                ldsm_x4(kh4, kvb + offB);
                ldsm_x4(kl4, kvb + FA_KL_O + offB);
                mma_bf16(s[2 * jj], ah, kh4);
                mma_bf16(s[2 * jj], ah, kl4);
                mma_bf16(s[2 * jj], al, kh4);
                mma_bf16(s[2 * jj + 1], ah, kh4 + 2);
                mma_bf16(s[2 * jj + 1], ah, kl4 + 2);
                mma_bf16(s[2 * jj + 1], al, kh4 + 2);
            }
        }

        // ---- warp-local online softmax (rows fr and fr+8) ----
        float rm0 = s[0][0], rm1 = s[0][2];
#pragma unroll
        for (int j = 0; j < 8; j++) {
            rm0 = fmaxf(rm0, fmaxf(s[j][0], s[j][1]));
            rm1 = fmaxf(rm1, fmaxf(s[j][2], s[j][3]));
        }
        rm0 = fmaxf(rm0, __shfl_xor_sync(0xffffffffu, rm0, 1));
        rm0 = fmaxf(rm0, __shfl_xor_sync(0xffffffffu, rm0, 2));
        rm1 = fmaxf(rm1, __shfl_xor_sync(0xffffffffu, rm1, 1));
        rm1 = fmaxf(rm1, __shfl_xor_sync(0xffffffffu, rm1, 2));
        float mn0 = fmaxf(m0, rm0), mn1 = fmaxf(m1, rm1);
        float a0 = __expf(m0 - mn0), a1 = __expf(m1 - mn1);
        m0 = mn0; m1 = mn1;

        uint32_t pph[8][2], ppl[8][2];
        float rs0 = 0.f, rs1 = 0.f;
#pragma unroll
        for (int j = 0; j < 8; j++) {
            float p0 = __expf(s[j][0] - mn0);
            float p1 = __expf(s[j][1] - mn0);
            float p2 = __expf(s[j][2] - mn1);
            float p3 = __expf(s[j][3] - mn1);
            rs0 += p0 + p1; rs1 += p2 + p3;
            __nv_bfloat16 h0, q0, h1, q1, h2, q2, h3, q3;
            bsplit(p0, h0, q0); bsplit(p1, h1, q1);
            bsplit(p2, h2, q2); bsplit(p3, h3, q3);
            __nv_bfloat162 t;
            t = mk2(h0, h1); pph[j][0] = *reinterpret_cast<uint32_t*>(&t);
            t = mk2(h2, h3); pph[j][1] = *reinterpret_cast<uint32_t*>(&t);
            t = mk2(q0, q1); ppl[j][0] = *reinterpret_cast<uint32_t*>(&t);
            t = mk2(q2, q3); ppl[j][1] = *reinterpret_cast<uint32_t*>(&t);
        }
        rs0 += __shfl_xor_sync(0xffffffffu, rs0, 1);
        rs0 += __shfl_xor_sync(0xffffffffu, rs0, 2);
        rs1 += __shfl_xor_sync(0xffffffffu, rs1, 1);
        rs1 += __shfl_xor_sync(0xffffffffu, rs1, 2);
        l0 = l0 * a0 + rs0;
        l1 = l1 * a1 + rs1;

#pragma unroll
        for (int j = 0; j < 8; j++) {
            o[j][0] *= a0; o[j][1] *= a0;
            o[j][2] *= a1; o[j][3] *= a1;
        }

        // ---- O += P V (bf16x3), P fragments straight from registers ----
#pragma unroll
        for (int kt = 0; kt < 4; kt++) {
            uint32_t pAh[4] = {pph[2 * kt][0], pph[2 * kt][1],
                               pph[2 * kt + 1][0], pph[2 * kt + 1][1]};
            uint32_t pAl[4] = {ppl[2 * kt][0], ppl[2 * kt][1],
                               ppl[2 * kt + 1][0], ppl[2 * kt + 1][1]};
#pragma unroll
            for (int jj = 0; jj < 4; jj++) {
                uint32_t vh4[4], vl4[4];
                uint32_t offV = SWZ128((kt * 16 + vRow) * 128 + (jj * 16 + vColOff) * 2);
                ldsm_x4t(vh4, kvb + FA_VH_O + offV);
                ldsm_x4t(vl4, kvb + FA_VL_O + offV);
                mma_bf16(o[2 * jj], pAh, vh4);
                mma_bf16(o[2 * jj], pAh, vl4);
                mma_bf16(o[2 * jj], pAl, vh4);
                mma_bf16(o[2 * jj + 1], pAh, vh4 + 2);
                mma_bf16(o[2 * jj + 1], pAh, vl4 + 2);
                mma_bf16(o[2 * jj + 1], pAl, vh4 + 2);
            }
        }
        if (jt + 1 < SEQ / 64) CP_WAIT0();
        __syncthreads();
    }

    // ---- epilogue: normalize, split, store [b,n,h,e] ----
    float inv0 = 1.f / l0, inv1 = 1.f / l1;
    const int r0g = qt * 128 + qrow + fr;
#pragma unroll
    for (int j = 0; j < 8; j++) {
        int col = j * 8 + fc;
        __nv_bfloat16 h0, q0, h1, q1;
        bsplit(o[j][0] * inv0, h0, q0); bsplit(o[j][1] * inv0, h1, q1);
        *reinterpret_cast<__nv_bfloat162*>(Oh + base + (size_t)r0g * 1024 + col) = mk2(h0, h1);
        *reinterpret_cast<__nv_bfloat162*>(Ol + base + (size_t)r0g * 1024 + col) = mk2(q0, q1);
        bsplit(o[j][2] * inv1, h0, q0); bsplit(o[j][3] * inv1, h1, q1);
        *reinterpret_cast<__nv_bfloat162*>(Oh + base + (size_t)(r0g + 8) * 1024 + col) = mk2(h0, h1);
        *reinterpret_cast<__nv_bfloat162*>(Ol + base + (size_t)(r0g + 8) * 1024 + col) = mk2(q0, q1);
    }
}

// ---------------- launch ------------------------------------------------------
extern "C" void kernel_launch(void* const* d_in, const int* in_sizes, int n_in,
                              void* d_out, int out_size) {
    const float* tokens = (const float*)d_in[0];
    const float* wq = (const float*)d_in[1];
    const float* wk = (const float*)d_in[2];
    const float* wv = (const float*)d_in[3];
    const float* wo = (const float*)d_in[4];
    float* out = (float*)d_out;

    __nv_bfloat16 *tokh, *tokl, *qh, *ql, *kh, *kl, *vh, *vl, *aggh, *aggl;
    __nv_bfloat16 *wqh, *wql, *wkh, *wkl, *wvh, *wvl, *woh, *wol;
    cudaGetSymbolAddress((void**)&tokh, g_tokh);
    cudaGetSymbolAddress((void**)&tokl, g_tokl);
    cudaGetSymbolAddress((void**)&qh, g_qh);
    cudaGetSymbolAddress((void**)&ql, g_ql);
    cudaGetSymbolAddress((void**)&kh, g_kh);
    cudaGetSymbolAddress((void**)&kl, g_kl);
    cudaGetSymbolAddress((void**)&vh, g_vh);
    cudaGetSymbolAddress((void**)&vl, g_vl);
    cudaGetSymbolAddress((void**)&aggh, g_aggh);
    cudaGetSymbolAddress((void**)&aggl, g_aggl);
    cudaGetSymbolAddress((void**)&wqh, g_wqh);
    cudaGetSymbolAddress((void**)&wql, g_wql);
    cudaGetSymbolAddress((void**)&wkh, g_wkh);
    cudaGetSymbolAddress((void**)&wkl, g_wkl);
    cudaGetSymbolAddress((void**)&wvh, g_wvh);
    cudaGetSymbolAddress((void**)&wvl, g_wvl);
    cudaGetSymbolAddress((void**)&woh, g_woh);
    cudaGetSymbolAddress((void**)&wol, g_wol);

    split_act<<<(BS * DIM / 4 + 255) / 256, 256>>>(
        (const float4*)tokens, tokh, tokl, BS * DIM / 4);
    pack_w<<<(DIM * DIM + 255) / 256, 256>>>(wq, wk, wv, wo);

    cudaFuncSetAttribute(gemm_qkv, cudaFuncAttributeMaxDynamicSharedMemorySize,
                         GS2_TOTAL);
    cudaFuncSetAttribute(gemm_wo, cudaFuncAttributeMaxDynamicSharedMemorySize,
                         GS2_TOTAL);

    QKVArgs args;
    args.bh[0] = wqh; args.bl[0] = wql; args.ch[0] = qh; args.cl[0] = ql;
    args.bh[1] = wkh; args.bl[1] = wkl; args.ch[1] = kh; args.cl[1] = kl;
    args.bh[2] = wvh; args.bl[2] = wvl; args.ch[2] = vh; args.cl[2] = vl;

    dim3 gqkv(DIM / 64, BS / 128, 3);
    gemm_qkv<<<gqkv, 256, GS2_TOTAL>>>(tokh, tokl, args);

    cudaFuncSetAttribute(flash_attn_mma,
                         cudaFuncAttributeMaxDynamicSharedMemorySize, FA_TOTAL);
    flash_attn_mma<<<dim3(SEQ / 128, BATCH * HEADS), 256, FA_TOTAL>>>(
        qh, ql, kh, kl, vh, vl, aggh, aggl);

    dim3 gp(DIM / 64, BS / 128);
    gemm_wo<<<gp, 256, GS2_TOTAL>>>(aggh, aggl, woh, wol, out);
}

// round 7
// speedup vs baseline: 3.2849x; 1.0149x over previous
#include <cuda_runtime.h>
#include <cuda_bf16.h>
#include <cstdint>

#define BATCH 2
#define SEQ 2048
#define DIM 1024
#define HEADS 16
#define DHEAD 64
#define BS (BATCH*SEQ)   // 4096

// ---------------- scratch (device globals; no allocations allowed) ----------
__device__ __nv_bfloat16 g_tokh[BS*DIM], g_tokl[BS*DIM];
__device__ __nv_bfloat16 g_qh[BS*DIM], g_ql[BS*DIM];
__device__ __nv_bfloat16 g_kh[BS*DIM], g_kl[BS*DIM];
__device__ __nv_bfloat16 g_vh[BS*DIM], g_vl[BS*DIM];
__device__ __nv_bfloat16 g_aggh[BS*DIM], g_aggl[BS*DIM];
__device__ __nv_bfloat16 g_wqh[DIM*DIM], g_wql[DIM*DIM];
__device__ __nv_bfloat16 g_wkh[DIM*DIM], g_wkl[DIM*DIM];
__device__ __nv_bfloat16 g_wvh[DIM*DIM], g_wvl[DIM*DIM];
__device__ __nv_bfloat16 g_woh[DIM*DIM], g_wol[DIM*DIM];

// ---------------- helpers ----------------------------------------------------
__device__ __forceinline__ uint32_t smem_u32(const void* p) {
    uint32_t a;
    asm("{ .reg .u64 t; cvta.to.shared.u64 t, %1; cvt.u32.u64 %0, t; }"
        : "=r"(a) : "l"(p));
    return a;
}
#define SWZ128(o) ((o) ^ (((o) >> 3) & 0x70))

__device__ __forceinline__ void cp16(uint32_t saddr, const void* gptr) {
    asm volatile("cp.async.cg.shared.global [%0], [%1], 16;"
                 :: "r"(saddr), "l"(gptr));
}
#define CP_COMMIT() asm volatile("cp.async.commit_group;" ::: "memory")
#define CP_WAIT0()  asm volatile("cp.async.wait_group 0;" ::: "memory")

__device__ __forceinline__ void ldsm_x4(uint32_t* r, uint32_t addr) {
    asm volatile("ldmatrix.sync.aligned.m8n8.x4.shared.b16 {%0,%1,%2,%3}, [%4];"
                 : "=r"(r[0]), "=r"(r[1]), "=r"(r[2]), "=r"(r[3]) : "r"(addr));
}
__device__ __forceinline__ void ldsm_x2(uint32_t* r, uint32_t addr) {
    asm volatile("ldmatrix.sync.aligned.m8n8.x2.shared.b16 {%0,%1}, [%2];"
                 : "=r"(r[0]), "=r"(r[1]) : "r"(addr));
}
__device__ __forceinline__ void ldsm_x4t(uint32_t* r, uint32_t addr) {
    asm volatile("ldmatrix.sync.aligned.m8n8.x4.trans.shared.b16 {%0,%1,%2,%3}, [%4];"
                 : "=r"(r[0]), "=r"(r[1]), "=r"(r[2]), "=r"(r[3]) : "r"(addr));
}
__device__ __forceinline__ void mma_bf16(float* c, const uint32_t* a, const uint32_t* b) {
    asm volatile(
        "mma.sync.aligned.m16n8k16.row.col.f32.bf16.bf16.f32 "
        "{%0,%1,%2,%3}, {%4,%5,%6,%7}, {%8,%9}, {%0,%1,%2,%3};"
        : "+f"(c[0]), "+f"(c[1]), "+f"(c[2]), "+f"(c[3])
        : "r"(a[0]), "r"(a[1]), "r"(a[2]), "r"(a[3]), "r"(b[0]), "r"(b[1]));
}
__device__ __forceinline__ void bsplit(float v, __nv_bfloat16& h, __nv_bfloat16& l) {
    h = __float2bfloat16(v);
    l = __float2bfloat16(v - __bfloat162float(h));
}
__device__ __forceinline__ __nv_bfloat162 mk2(__nv_bfloat16 a, __nv_bfloat16 b) {
    __nv_bfloat162 t; t.x = a; t.y = b; return t;
}
// packed split: (a,b) -> hi bf16x2 word + lo bf16x2 word
__device__ __forceinline__ void bsplit2(float a, float b, uint32_t& hi, uint32_t& lo) {
    __nv_bfloat162 h = __floats2bfloat162_rn(a, b);
    float2 f = __bfloat1622float2(h);
    __nv_bfloat162 l = __floats2bfloat162_rn(a - f.x, b - f.y);
    hi = *reinterpret_cast<uint32_t*>(&h);
    lo = *reinterpret_cast<uint32_t*>(&l);
}

// ---------------- split / pack kernels ---------------------------------------
__global__ void split_act(const float4* __restrict__ x,
                          __nv_bfloat16* __restrict__ hi,
                          __nv_bfloat16* __restrict__ lo, int n4) {
    int i = blockIdx.x * blockDim.x + threadIdx.x;
    if (i >= n4) return;
    float4 v = x[i];
    uint32_t h01, l01, h23, l23;
    bsplit2(v.x, v.y, h01, l01);
    bsplit2(v.z, v.w, h23, l23);
    uint32_t* H = reinterpret_cast<uint32_t*>(hi);
    uint32_t* L = reinterpret_cast<uint32_t*>(lo);
    H[2 * i] = h01; H[2 * i + 1] = h23;
    L[2 * i] = l01; L[2 * i + 1] = l23;
}

__global__ void pack_w(const float* __restrict__ wq, const float* __restrict__ wk,
                       const float* __restrict__ wv, const float* __restrict__ wo) {
    int idx = blockIdx.x * blockDim.x + threadIdx.x;
    if (idx >= DIM * DIM) return;
    int n = idx >> 10;
    int k = idx & 1023;
    int h = n >> 6, e = n & 63;
    int src = (h * DIM + k) * DHEAD + e;
    bsplit(wq[src] * 0.125f, g_wqh[idx], g_wql[idx]);   // SCALE = 64^-0.5
    bsplit(wk[src], g_wkh[idx], g_wkl[idx]);
    bsplit(wv[src], g_wvh[idx], g_wvl[idx]);
    bsplit(wo[k * DIM + n], g_woh[idx], g_wol[idx]);
}

// ---------------- bf16x3 GEMM (HMMA + cp.async 2-stage) -----------------------
#define ST_AL 16384
#define ST_BH 32768
#define ST_BL 40960
#define ST_SZ 49152
#define GS2_TOTAL (2*ST_SZ)

template <bool SPLIT>
__device__ __forceinline__ void gemm_body(
    const __nv_bfloat16* __restrict__ Ah, const __nv_bfloat16* __restrict__ Al,
    const __nv_bfloat16* __restrict__ Bh, const __nv_bfloat16* __restrict__ Bl,
    float* __restrict__ C, __nv_bfloat16* __restrict__ Ch,
    __nv_bfloat16* __restrict__ Cl, char* smem) {
    const uint32_t sb = smem_u32(smem);
    const int tid = threadIdx.x;
    const int lane = tid & 31;
    const int wid = tid >> 5;
    const int warp_m = wid & 3;
    const int warp_n = wid >> 2;
    const int row0 = blockIdx.y * 128;
    const int col0 = blockIdx.x * 64;

    const uint4* gA[2] = {reinterpret_cast<const uint4*>(Ah + (size_t)row0 * DIM),
                          reinterpret_cast<const uint4*>(Al + (size_t)row0 * DIM)};
    const uint4* gB[2] = {reinterpret_cast<const uint4*>(Bh + (size_t)col0 * DIM),
                          reinterpret_cast<const uint4*>(Bl + (size_t)col0 * DIM)};

    const int lrow = tid >> 3, lcol = tid & 7;

    auto load_stage = [&](int cidx, int s) {
        const int k0u = cidx * 8;
        const uint32_t sbase = sb + s * ST_SZ;
#pragma unroll
        for (int m = 0; m < 2; m++) {
#pragma unroll
            for (int r4 = 0; r4 < 4; r4++) {
                int row = lrow + r4 * 32;
                uint32_t off = SWZ128(row * 128 + lcol * 16);
                cp16(sbase + (m ? ST_AL : 0) + off, gA[m] + row * 128 + k0u + lcol);
            }
#pragma unroll
            for (int r4 = 0; r4 < 2; r4++) {
                int row = lrow + r4 * 32;
                uint32_t off = SWZ128(row * 128 + lcol * 16);
                cp16(sbase + (m ? ST_BL : ST_BH) + off, gB[m] + row * 128 + k0u + lcol);
            }
        }
        CP_COMMIT();
    };

    int amask[2], abase[2];
#pragma unroll
    for (int i = 0; i < 2; i++) {
        int r = warp_m * 32 + i * 16 + (lane & 15);
        amask[i] = (r & 7) << 4;
        abase[i] = r * 128 + ((lane >> 4) & 1) * 16;
    }
    const int brow = warp_n * 32 + (lane & 7);
    const int bmaskbase = ((lane & 15) >> 3) * 16;

    float acc[2][4][4] = {};

    load_stage(0, 0);
    CP_WAIT0();
    __syncthreads();

    for (int c = 0; c < 16; c++) {
        if (c < 15) load_stage(c + 1, (c + 1) & 1);
        const uint32_t sbase = sb + (c & 1) * ST_SZ;
#pragma unroll
        for (int ks = 0; ks < 4; ks++) {
            uint32_t ah[2][4], al[2][4], bh[4][2], bl[4][2];
#pragma unroll
            for (int i = 0; i < 2; i++) {
                uint32_t offA = (abase[i] + ks * 32) ^ amask[i];
                ldsm_x4(ah[i], sbase + offA);
                ldsm_x4(al[i], sbase + ST_AL + offA);
            }
#pragma unroll
            for (int j = 0; j < 4; j++) {
                int r = brow + j * 8;
                uint32_t offB = (r * 128 + bmaskbase + ks * 32) ^ ((r & 7) << 4);
                ldsm_x2(bh[j], sbase + ST_BH + offB);
                ldsm_x2(bl[j], sbase + ST_BL + offB);
            }
            // term-major: accumulator reuse distance = 8
#pragma unroll
            for (int i = 0; i < 2; i++)
#pragma unroll
                for (int j = 0; j < 4; j++)
                    mma_bf16(acc[i][j], ah[i], bh[j]);
#pragma unroll
            for (int i = 0; i < 2; i++)
#pragma unroll
                for (int j = 0; j < 4; j++)
                    mma_bf16(acc[i][j], ah[i], bl[j]);
#pragma unroll
            for (int i = 0; i < 2; i++)
#pragma unroll
                for (int j = 0; j < 4; j++)
                    mma_bf16(acc[i][j], al[i], bh[j]);
        }
        if (c < 15) {
            CP_WAIT0();
            __syncthreads();
        }
    }

    const int fr = lane >> 2, fc = (lane & 3) * 2;
#pragma unroll
    for (int i = 0; i < 2; i++) {
        int rbase = row0 + warp_m * 32 + i * 16 + fr;
#pragma unroll
        for (int j = 0; j < 4; j++) {
            int col = col0 + warp_n * 32 + j * 8 + fc;
            if (SPLIT) {
                uint32_t h01, l01;
                bsplit2(acc[i][j][0], acc[i][j][1], h01, l01);
                *reinterpret_cast<uint32_t*>(&Ch[(size_t)rbase * DIM + col]) = h01;
                *reinterpret_cast<uint32_t*>(&Cl[(size_t)rbase * DIM + col]) = l01;
                bsplit2(acc[i][j][2], acc[i][j][3], h01, l01);
                *reinterpret_cast<uint32_t*>(&Ch[(size_t)(rbase + 8) * DIM + col]) = h01;
                *reinterpret_cast<uint32_t*>(&Cl[(size_t)(rbase + 8) * DIM + col]) = l01;
            } else {
                *reinterpret_cast<float2*>(&C[(size_t)rbase * DIM + col]) =
                    make_float2(acc[i][j][0], acc[i][j][1]);
                *reinterpret_cast<float2*>(&C[(size_t)(rbase + 8) * DIM + col]) =
                    make_float2(acc[i][j][2], acc[i][j][3]);
            }
        }
    }
}

struct QKVArgs {
    const __nv_bfloat16* bh[3];
    const __nv_bfloat16* bl[3];
    __nv_bfloat16* ch[3];
    __nv_bfloat16* cl[3];
};

__global__ __launch_bounds__(256, 2) void gemm_qkv(
    const __nv_bfloat16* __restrict__ Ah, const __nv_bfloat16* __restrict__ Al,
    QKVArgs args) {
    extern __shared__ char smem[];
    const int z = blockIdx.z;
    gemm_body<true>(Ah, Al, args.bh[z], args.bl[z], nullptr,
                    args.ch[z], args.cl[z], smem);
}

__global__ __launch_bounds__(256, 2) void gemm_wo(
    const __nv_bfloat16* __restrict__ Ah, const __nv_bfloat16* __restrict__ Al,
    const __nv_bfloat16* __restrict__ Bh, const __nv_bfloat16* __restrict__ Bl,
    float* __restrict__ C) {
    extern __shared__ char smem[];
    gemm_body<false>(Ah, Al, Bh, Bl, C, nullptr, nullptr, smem);
}

// ---------------- flash attention (FA2-style, register-resident P) ----------
// 8 warps x 16 query rows each; each warp spans full N=64 KV width.
// smem: QH 0 (16K) | QL 16K | KV stage0 @32K (KH,KL,VH,VL 8K each) | KV stage1 @64K
#define FA_QL 16384
#define FA_KV0 32768
#define FA_KVS 32768
#define FA_KL_O 8192
#define FA_VH_O 16384
#define FA_VL_O 24576
#define FA_TOTAL 98304

__global__ __launch_bounds__(256, 2) void flash_attn_mma(
    const __nv_bfloat16* __restrict__ Qh, const __nv_bfloat16* __restrict__ Ql,
    const __nv_bfloat16* __restrict__ Kh, const __nv_bfloat16* __restrict__ Kl,
    const __nv_bfloat16* __restrict__ Vh, const __nv_bfloat16* __restrict__ Vl,
    __nv_bfloat16* __restrict__ Oh, __nv_bfloat16* __restrict__ Ol) {
    extern __shared__ char smem[];
    const uint32_t sb = smem_u32(smem);
    const int tid = threadIdx.x, lane = tid & 31, wid = tid >> 5;
    const int qt = blockIdx.x, bhid = blockIdx.y;
    const int b = bhid >> 4, h = bhid & 15;
    const size_t base = ((size_t)(b * SEQ) * HEADS + h) * DHEAD;
    const uint4* Qhp = reinterpret_cast<const uint4*>(Qh + base);
    const uint4* Qlp = reinterpret_cast<const uint4*>(Ql + base);
    const uint4* Khp = reinterpret_cast<const uint4*>(Kh + base);
    const uint4* Klp = reinterpret_cast<const uint4*>(Kl + base);
    const uint4* Vhp = reinterpret_cast<const uint4*>(Vh + base);
    const uint4* Vlp = reinterpret_cast<const uint4*>(Vl + base);

    const int lrw = tid >> 3, lcl = tid & 7;

    auto load_kv = [&](int jt, int s) {
        const uint32_t kvb = sb + FA_KV0 + s * FA_KVS;
#pragma unroll
        for (int r4 = 0; r4 < 2; r4++) {
            int row = lrw + r4 * 32;
            uint32_t off = SWZ128(row * 128 + lcl * 16);
            int g = (jt * 64 + row) * 128 + lcl;
            cp16(kvb + off, Khp + g);
            cp16(kvb + FA_KL_O + off, Klp + g);
            cp16(kvb + FA_VH_O + off, Vhp + g);
            cp16(kvb + FA_VL_O + off, Vlp + g);
        }
        CP_COMMIT();
    };

    load_kv(0, 0);
#pragma unroll
    for (int r4 = 0; r4 < 4; r4++) {
        int row = lrw + r4 * 32;
        uint32_t off = SWZ128(row * 128 + lcl * 16);
        int g = (qt * 128 + row) * 128 + lcl;
        *reinterpret_cast<uint4*>(smem + off) = Qhp[g];
        *reinterpret_cast<uint4*>(smem + FA_QL + off) = Qlp[g];
    }

    float m0 = -1e30f, m1 = -1e30f, l0 = 0.f, l1 = 0.f;
    float o[8][4] = {};
    const int fr = lane >> 2, fc = (lane & 3) * 2;
    const int qrow = wid * 16;
    const int aRow = lane & 15, aCol = (lane >> 4) * 16;       // Q A-frag
    const int kRow = ((lane >> 4) & 1) * 8 + (lane & 7);       // K B-frag x4
    const int kHalf = ((lane >> 3) & 1) * 16;
    const int vRow = lane & 15;                                 // V B-frag x4t
    const int vColOff = ((lane >> 4) & 1) * 8;

    CP_WAIT0();
    __syncthreads();

    for (int jt = 0; jt < SEQ / 64; jt++) {
        const uint32_t kvb = sb + FA_KV0 + (jt & 1) * FA_KVS;
        if (jt + 1 < SEQ / 64) load_kv(jt + 1, (jt + 1) & 1);

        // ---- S = Q K^T (bf16x3), term-major in jj-pairs ----
        float s[8][4] = {};
#pragma unroll
        for (int ks = 0; ks < 4; ks++) {
            uint32_t ah[4], al[4];
            uint32_t offA = SWZ128((qrow + aRow) * 128 + ks * 32 + aCol);
            ldsm_x4(ah, sb + offA);
            ldsm_x4(al, sb + FA_QL + offA);
#pragma unroll
            for (int jp = 0; jp < 2; jp++) {
                uint32_t kh4[2][4], kl4[2][4];
#pragma unroll
                for (int u = 0; u < 2; u++) {
                    int jj = jp * 2 + u;
                    uint32_t offB = SWZ128((jj * 16 + kRow) * 128 + ks * 32 + kHalf);
                    ldsm_x4(kh4[u], kvb + offB);
                    ldsm_x4(kl4[u], kvb + FA_KL_O + offB);
                }
#pragma unroll
                for (int u = 0; u < 2; u++) {
                    int jj = jp * 2 + u;
                    mma_bf16(s[2 * jj], ah, kh4[u]);
                    mma_bf16(s[2 * jj + 1], ah, kh4[u] + 2);
                }
#pragma unroll
                for (int u = 0; u < 2; u++) {
                    int jj = jp * 2 + u;
                    mma_bf16(s[2 * jj], ah, kl4[u]);
                    mma_bf16(s[2 * jj + 1], ah, kl4[u] + 2);
                }
#pragma unroll
                for (int u = 0; u < 2; u++) {
                    int jj = jp * 2 + u;
                    mma_bf16(s[2 * jj], al, kh4[u]);
                    mma_bf16(s[2 * jj + 1], al, kh4[u] + 2);
                }
            }
        }

        // ---- warp-local row max ----
        float rm0 = s[0][0], rm1 = s[0][2];
#pragma unroll
        for (int j = 0; j < 8; j++) {
            rm0 = fmaxf(rm0, fmaxf(s[j][0], s[j][1]));
            rm1 = fmaxf(rm1, fmaxf(s[j][2], s[j][3]));
        }
        rm0 = fmaxf(rm0, __shfl_xor_sync(0xffffffffu, rm0, 1));
        rm0 = fmaxf(rm0, __shfl_xor_sync(0xffffffffu, rm0, 2));
        rm1 = fmaxf(rm1, __shfl_xor_sync(0xffffffffu, rm1, 1));
        rm1 = fmaxf(rm1, __shfl_xor_sync(0xffffffffu, rm1, 2));
        float mn0 = fmaxf(m0, rm0), mn1 = fmaxf(m1, rm1);
        float a0 = __expf(m0 - mn0), a1 = __expf(m1 - mn1);
        m0 = mn0; m1 = mn1;

        // rescale O
#pragma unroll
        for (int j = 0; j < 8; j++) {
            o[j][0] *= a0; o[j][1] *= a0;
            o[j][2] *= a1; o[j][3] *= a1;
        }

        // ---- PV with fused exp/pack (overlaps MUFU/FMA with tensor) ----
        float rs0 = 0.f, rs1 = 0.f;
#pragma unroll
        for (int kt = 0; kt < 4; kt++) {
            uint32_t pAh[4], pAl[4];
#pragma unroll
            for (int u = 0; u < 2; u++) {
                int j = 2 * kt + u;
                float p0 = __expf(s[j][0] - mn0);
                float p1 = __expf(s[j][1] - mn0);
                float p2 = __expf(s[j][2] - mn1);
                float p3 = __expf(s[j][3] - mn1);
                rs0 += p0 + p1; rs1 += p2 + p3;
                bsplit2(p0, p1, pAh[2 * u], pAl[2 * u]);
                bsplit2(p2, p3, pAh[2 * u + 1], pAl[2 * u + 1]);
            }
#pragma unroll
            for (int jp = 0; jp < 2; jp++) {
                uint32_t vh4[2][4], vl4[2][4];
#pragma unroll
                for (int u = 0; u < 2; u++) {
                    int jj = jp * 2 + u;
                    uint32_t offV = SWZ128((kt * 16 + vRow) * 128 + (jj * 16 + vColOff) * 2);
                    ldsm_x4t(vh4[u], kvb + FA_VH_O + offV);
                    ldsm_x4t(vl4[u], kvb + FA_VL_O + offV);
                }
#pragma unroll
                for (int u = 0; u < 2; u++) {
                    int jj = jp * 2 + u;
                    mma_bf16(o[2 * jj], pAh, vh4[u]);
                    mma_bf16(o[2 * jj + 1], pAh, vh4[u] + 2);
                }
#pragma unroll
                for (int u = 0; u < 2; u++) {
                    int jj = jp * 2 + u;
                    mma_bf16(o[2 * jj], pAh, vl4[u]);
                    mma_bf16(o[2 * jj + 1], pAh, vl4[u] + 2);
                }
#pragma unroll
                for (int u = 0; u < 2; u++) {
                    int jj = jp * 2 + u;
                    mma_bf16(o[2 * jj], pAl, vh4[u]);
                    mma_bf16(o[2 * jj + 1], pAl, vh4[u] + 2);
                }
            }
        }
        rs0 += __shfl_xor_sync(0xffffffffu, rs0, 1);
        rs0 += __shfl_xor_sync(0xffffffffu, rs0, 2);
        rs1 += __shfl_xor_sync(0xffffffffu, rs1, 1);
        rs1 += __shfl_xor_sync(0xffffffffu, rs1, 2);
        l0 = l0 * a0 + rs0;
        l1 = l1 * a1 + rs1;

        if (jt + 1 < SEQ / 64) CP_WAIT0();
        __syncthreads();
    }

    // ---- epilogue: normalize, split, store [b,n,h,e] ----
    float inv0 = 1.f / l0, inv1 = 1.f / l1;
    const int r0g = qt * 128 + qrow + fr;
#pragma unroll
    for (int j = 0; j < 8; j++) {
        int col = j * 8 + fc;
        uint32_t h01, l01;
        bsplit2(o[j][0] * inv0, o[j][1] * inv0, h01, l01);
        *reinterpret_cast<uint32_t*>(Oh + base + (size_t)r0g * 1024 + col) = h01;
        *reinterpret_cast<uint32_t*>(Ol + base + (size_t)r0g * 1024 + col) = l01;
        bsplit2(o[j][2] * inv1, o[j][3] * inv1, h01, l01);
        *reinterpret_cast<uint32_t*>(Oh + base + (size_t)(r0g + 8) * 1024 + col) = h01;
        *reinterpret_cast<uint32_t*>(Ol + base + (size_t)(r0g + 8) * 1024 + col) = l01;
    }
}

// ---------------- launch ------------------------------------------------------
extern "C" void kernel_launch(void* const* d_in, const int* in_sizes, int n_in,
                              void* d_out, int out_size) {
    const float* tokens = (const float*)d_in[0];
    const float* wq = (const float*)d_in[1];
    const float* wk = (const float*)d_in[2];
    const float* wv = (const float*)d_in[3];
    const float* wo = (const float*)d_in[4];
    float* out = (float*)d_out;

    __nv_bfloat16 *tokh, *tokl, *qh, *ql, *kh, *kl, *vh, *vl, *aggh, *aggl;
    __nv_bfloat16 *wqh, *wql, *wkh, *wkl, *wvh, *wvl, *woh, *wol;
    cudaGetSymbolAddress((void**)&tokh, g_tokh);
    cudaGetSymbolAddress((void**)&tokl, g_tokl);
    cudaGetSymbolAddress((void**)&qh, g_qh);
    cudaGetSymbolAddress((void**)&ql, g_ql);
    cudaGetSymbolAddress((void**)&kh, g_kh);
    cudaGetSymbolAddress((void**)&kl, g_kl);
    cudaGetSymbolAddress((void**)&vh, g_vh);
    cudaGetSymbolAddress((void**)&vl, g_vl);
    cudaGetSymbolAddress((void**)&aggh, g_aggh);
    cudaGetSymbolAddress((void**)&aggl, g_aggl);
    cudaGetSymbolAddress((void**)&wqh, g_wqh);
    cudaGetSymbolAddress((void**)&wql, g_wql);
    cudaGetSymbolAddress((void**)&wkh, g_wkh);
    cudaGetSymbolAddress((void**)&wkl, g_wkl);
    cudaGetSymbolAddress((void**)&wvh, g_wvh);
    cudaGetSymbolAddress((void**)&wvl, g_wvl);
    cudaGetSymbolAddress((void**)&woh, g_woh);
    cudaGetSymbolAddress((void**)&wol, g_wol);

    split_act<<<(BS * DIM / 4 + 255) / 256, 256>>>(
        (const float4*)tokens, tokh, tokl, BS * DIM / 4);
    pack_w<<<(DIM * DIM + 255) / 256, 256>>>(wq, wk, wv, wo);

    cudaFuncSetAttribute(gemm_qkv, cudaFuncAttributeMaxDynamicSharedMemorySize,
                         GS2_TOTAL);
    cudaFuncSetAttribute(gemm_wo, cudaFuncAttributeMaxDynamicSharedMemorySize,
                         GS2_TOTAL);

    QKVArgs args;
    args.bh[0] = wqh; args.bl[0] = wql; args.ch[0] = qh; args.cl[0] = ql;
    args.bh[1] = wkh; args.bl[1] = wkl; args.ch[1] = kh; args.cl[1] = kl;
    args.bh[2] = wvh; args.bl[2] = wvl; args.ch[2] = vh; args.cl[2] = vl;

    dim3 gqkv(DIM / 64, BS / 128, 3);
    gemm_qkv<<<gqkv, 256, GS2_TOTAL>>>(tokh, tokl, args);

    cudaFuncSetAttribute(flash_attn_mma,
                         cudaFuncAttributeMaxDynamicSharedMemorySize, FA_TOTAL);
    flash_attn_mma<<<dim3(SEQ / 128, BATCH * HEADS), 256, FA_TOTAL>>>(
        qh, ql, kh, kl, vh, vl, aggh, aggl);

    dim3 gp(DIM / 64, BS / 128);
    gemm_wo<<<gp, 256, GS2_TOTAL>>>(aggh, aggl, woh, wol, out);
}

// round 8
// speedup vs baseline: 3.9062x; 1.1892x over previous
#include <cuda_runtime.h>
#include <cuda_fp16.h>
#include <cstdint>

#define BATCH 2
#define SEQ 2048
#define DIM 1024
#define HEADS 16
#define DHEAD 64
#define BS (BATCH*SEQ)   // 4096

// ---------------- scratch (device globals; no allocations allowed) ----------
__device__ __half g_tokh[BS*DIM], g_tokl[BS*DIM];
__device__ __half g_qh[BS*DIM], g_ql[BS*DIM];
__device__ __half g_kh[BS*DIM], g_kl[BS*DIM];
__device__ __half g_vh[BS*DIM], g_vl[BS*DIM];
__device__ __half g_aggh[BS*DIM], g_aggl[BS*DIM];
__device__ __half g_wqh[DIM*DIM], g_wql[DIM*DIM];
__device__ __half g_wkh[DIM*DIM], g_wkl[DIM*DIM];
__device__ __half g_wvh[DIM*DIM], g_wvl[DIM*DIM];
__device__ __half g_woh[DIM*DIM], g_wol[DIM*DIM];

// ---------------- helpers ----------------------------------------------------
__device__ __forceinline__ uint32_t smem_u32(const void* p) {
    uint32_t a;
    asm("{ .reg .u64 t; cvta.to.shared.u64 t, %1; cvt.u32.u64 %0, t; }"
        : "=r"(a) : "l"(p));
    return a;
}
#define SWZ128(o) ((o) ^ (((o) >> 3) & 0x70))

__device__ __forceinline__ void cp16(uint32_t saddr, const void* gptr) {
    asm volatile("cp.async.cg.shared.global [%0], [%1], 16;"
                 :: "r"(saddr), "l"(gptr));
}
#define CP_COMMIT() asm volatile("cp.async.commit_group;" ::: "memory")
#define CP_WAIT0()  asm volatile("cp.async.wait_group 0;" ::: "memory")

__device__ __forceinline__ void ldsm_x4(uint32_t* r, uint32_t addr) {
    asm volatile("ldmatrix.sync.aligned.m8n8.x4.shared.b16 {%0,%1,%2,%3}, [%4];"
                 : "=r"(r[0]), "=r"(r[1]), "=r"(r[2]), "=r"(r[3]) : "r"(addr));
}
__device__ __forceinline__ void ldsm_x2(uint32_t* r, uint32_t addr) {
    asm volatile("ldmatrix.sync.aligned.m8n8.x2.shared.b16 {%0,%1}, [%2];"
                 : "=r"(r[0]), "=r"(r[1]) : "r"(addr));
}
__device__ __forceinline__ void ldsm_x4t(uint32_t* r, uint32_t addr) {
    asm volatile("ldmatrix.sync.aligned.m8n8.x4.trans.shared.b16 {%0,%1,%2,%3}, [%4];"
                 : "=r"(r[0]), "=r"(r[1]), "=r"(r[2]), "=r"(r[3]) : "r"(addr));
}
__device__ __forceinline__ void mma_f16(float* c, const uint32_t* a, const uint32_t* b) {
    asm volatile(
        "mma.sync.aligned.m16n8k16.row.col.f32.f16.f16.f32 "
        "{%0,%1,%2,%3}, {%4,%5,%6,%7}, {%8,%9}, {%0,%1,%2,%3};"
        : "+f"(c[0]), "+f"(c[1]), "+f"(c[2]), "+f"(c[3])
        : "r"(a[0]), "r"(a[1]), "r"(a[2]), "r"(a[3]), "r"(b[0]), "r"(b[1]));
}
__device__ __forceinline__ void hsplit(float v, __half& h, __half& l) {
    h = __float2half_rn(v);
    l = __float2half_rn(v - __half2float(h));
}
// packed split: (a,b) -> hi f16x2 word + lo f16x2 word
__device__ __forceinline__ void hsplit2(float a, float b, uint32_t& hi, uint32_t& lo) {
    __half2 h = __floats2half2_rn(a, b);
    float2 f = __half22float2(h);
    __half2 l = __floats2half2_rn(a - f.x, b - f.y);
    hi = *reinterpret_cast<uint32_t*>(&h);
    lo = *reinterpret_cast<uint32_t*>(&l);
}

// ---------------- split / pack kernels ---------------------------------------
__global__ void split_act(const float4* __restrict__ x,
                          __half* __restrict__ hi,
                          __half* __restrict__ lo, int n4) {
    int i = blockIdx.x * blockDim.x + threadIdx.x;
    if (i >= n4) return;
    float4 v = x[i];
    uint32_t h01, l01, h23, l23;
    hsplit2(v.x, v.y, h01, l01);
    hsplit2(v.z, v.w, h23, l23);
    uint32_t* H = reinterpret_cast<uint32_t*>(hi);
    uint32_t* L = reinterpret_cast<uint32_t*>(lo);
    H[2 * i] = h01; H[2 * i + 1] = h23;
    L[2 * i] = l01; L[2 * i + 1] = l23;
}

__global__ void pack_w(const float* __restrict__ wq, const float* __restrict__ wk,
                       const float* __restrict__ wv, const float* __restrict__ wo) {
    int idx = blockIdx.x * blockDim.x + threadIdx.x;
    if (idx >= DIM * DIM) return;
    int n = idx >> 10;
    int k = idx & 1023;
    int h = n >> 6, e = n & 63;
    int src = (h * DIM + k) * DHEAD + e;
    hsplit(wq[src] * 0.125f, g_wqh[idx], g_wql[idx]);   // SCALE = 64^-0.5
    hsplit(wk[src], g_wkh[idx], g_wkl[idx]);
    hsplit(wv[src], g_wvh[idx], g_wvl[idx]);
    hsplit(wo[k * DIM + n], g_woh[idx], g_wol[idx]);
}

// ---------------- fp16x3 GEMM (HMMA + cp.async 2-stage) -----------------------
#define ST_AL 16384
#define ST_BH 32768
#define ST_BL 40960
#define ST_SZ 49152
#define GS2_TOTAL (2*ST_SZ)

template <bool SPLIT>
__device__ __forceinline__ void gemm_body(
    const __half* __restrict__ Ah, const __half* __restrict__ Al,
    const __half* __restrict__ Bh, const __half* __restrict__ Bl,
    float* __restrict__ C, __half* __restrict__ Ch,
    __half* __restrict__ Cl, char* smem) {
    const uint32_t sb = smem_u32(smem);
    const int tid = threadIdx.x;
    const int lane = tid & 31;
    const int wid = tid >> 5;
    const int warp_m = wid & 3;
    const int warp_n = wid >> 2;
    const int row0 = blockIdx.y * 128;
    const int col0 = blockIdx.x * 64;

    const uint4* gA[2] = {reinterpret_cast<const uint4*>(Ah + (size_t)row0 * DIM),
                          reinterpret_cast<const uint4*>(Al + (size_t)row0 * DIM)};
    const uint4* gB[2] = {reinterpret_cast<const uint4*>(Bh + (size_t)col0 * DIM),
                          reinterpret_cast<const uint4*>(Bl + (size_t)col0 * DIM)};

    const int lrow = tid >> 3, lcol = tid & 7;

    auto load_stage = [&](int cidx, int s) {
        const int k0u = cidx * 8;
        const uint32_t sbase = sb + s * ST_SZ;
#pragma unroll
        for (int m = 0; m < 2; m++) {
#pragma unroll
            for (int r4 = 0; r4 < 4; r4++) {
                int row = lrow + r4 * 32;
                uint32_t off = SWZ128(row * 128 + lcol * 16);
                cp16(sbase + (m ? ST_AL : 0) + off, gA[m] + row * 128 + k0u + lcol);
            }
#pragma unroll
            for (int r4 = 0; r4 < 2; r4++) {
                int row = lrow + r4 * 32;
                uint32_t off = SWZ128(row * 128 + lcol * 16);
                cp16(sbase + (m ? ST_BL : ST_BH) + off, gB[m] + row * 128 + k0u + lcol);
            }
        }
        CP_COMMIT();
    };

    int amask[2], abase[2];
#pragma unroll
    for (int i = 0; i < 2; i++) {
        int r = warp_m * 32 + i * 16 + (lane & 15);
        amask[i] = (r & 7) << 4;
        abase[i] = r * 128 + ((lane >> 4) & 1) * 16;
    }
    const int brow = warp_n * 32 + (lane & 7);
    const int bmaskbase = ((lane & 15) >> 3) * 16;

    float acc[2][4][4] = {};

    load_stage(0, 0);
    CP_WAIT0();
    __syncthreads();

    for (int c = 0; c < 16; c++) {
        if (c < 15) load_stage(c + 1, (c + 1) & 1);
        const uint32_t sbase = sb + (c & 1) * ST_SZ;
#pragma unroll
        for (int ks = 0; ks < 4; ks++) {
            uint32_t ah[2][4], al[2][4], bh[4][2], bl[4][2];
#pragma unroll
            for (int i = 0; i < 2; i++) {
                uint32_t offA = (abase[i] + ks * 32) ^ amask[i];
                ldsm_x4(ah[i], sbase + offA);
                ldsm_x4(al[i], sbase + ST_AL + offA);
            }
#pragma unroll
            for (int j = 0; j < 4; j++) {
                int r = brow + j * 8;
                uint32_t offB = (r * 128 + bmaskbase + ks * 32) ^ ((r & 7) << 4);
                ldsm_x2(bh[j], sbase + ST_BH + offB);
                ldsm_x2(bl[j], sbase + ST_BL + offB);
            }
#pragma unroll
            for (int i = 0; i < 2; i++)
#pragma unroll
                for (int j = 0; j < 4; j++)
                    mma_f16(acc[i][j], ah[i], bh[j]);
#pragma unroll
            for (int i = 0; i < 2; i++)
#pragma unroll
                for (int j = 0; j < 4; j++)
                    mma_f16(acc[i][j], ah[i], bl[j]);
#pragma unroll
            for (int i = 0; i < 2; i++)
#pragma unroll
                for (int j = 0; j < 4; j++)
                    mma_f16(acc[i][j], al[i], bh[j]);
        }
        if (c < 15) {
            CP_WAIT0();
            __syncthreads();
        }
    }

    const int fr = lane >> 2, fc = (lane & 3) * 2;
#pragma unroll
    for (int i = 0; i < 2; i++) {
        int rbase = row0 + warp_m * 32 + i * 16 + fr;
#pragma unroll
        for (int j = 0; j < 4; j++) {
            int col = col0 + warp_n * 32 + j * 8 + fc;
            if (SPLIT) {
                uint32_t h01, l01;
                hsplit2(acc[i][j][0], acc[i][j][1], h01, l01);
                *reinterpret_cast<uint32_t*>(&Ch[(size_t)rbase * DIM + col]) = h01;
                *reinterpret_cast<uint32_t*>(&Cl[(size_t)rbase * DIM + col]) = l01;
                hsplit2(acc[i][j][2], acc[i][j][3], h01, l01);
                *reinterpret_cast<uint32_t*>(&Ch[(size_t)(rbase + 8) * DIM + col]) = h01;
                *reinterpret_cast<uint32_t*>(&Cl[(size_t)(rbase + 8) * DIM + col]) = l01;
            } else {
                *reinterpret_cast<float2*>(&C[(size_t)rbase * DIM + col]) =
                    make_float2(acc[i][j][0], acc[i][j][1]);
                *reinterpret_cast<float2*>(&C[(size_t)(rbase + 8) * DIM + col]) =
                    make_float2(acc[i][j][2], acc[i][j][3]);
            }
        }
    }
}

struct QKVArgs {
    const __half* bh[3];
    const __half* bl[3];
    __half* ch[3];
    __half* cl[3];
};

__global__ __launch_bounds__(256, 2) void gemm_qkv(
    const __half* __restrict__ Ah, const __half* __restrict__ Al,
    QKVArgs args) {
    extern __shared__ char smem[];
    const int z = blockIdx.z;
    gemm_body<true>(Ah, Al, args.bh[z], args.bl[z], nullptr,
                    args.ch[z], args.cl[z], smem);
}

__global__ __launch_bounds__(256, 2) void gemm_wo(
    const __half* __restrict__ Ah, const __half* __restrict__ Al,
    const __half* __restrict__ Bh, const __half* __restrict__ Bl,
    float* __restrict__ C) {
    extern __shared__ char smem[];
    gemm_body<false>(Ah, Al, Bh, Bl, C, nullptr, nullptr, smem);
}

// ---------------- flash attention (fp16; QK x3, PV x1) -----------------------
// 8 warps x 16 query rows each; each warp spans full N=64 KV width.
// smem: QH 0 (16K) | QL 16K | KV stage0 @32K (KH,KL,VH 8K each) | KV stage1 @56K
#define FA_QL 16384
#define FA_KV0 32768
#define FA_KVS 24576
#define FA_KL_O 8192
#define FA_VH_O 16384
#define FA_TOTAL (32768 + 2*24576)   // 81920

__global__ __launch_bounds__(256, 2) void flash_attn_mma(
    const __half* __restrict__ Qh, const __half* __restrict__ Ql,
    const __half* __restrict__ Kh, const __half* __restrict__ Kl,
    const __half* __restrict__ Vh,
    __half* __restrict__ Oh, __half* __restrict__ Ol) {
    extern __shared__ char smem[];
    const uint32_t sb = smem_u32(smem);
    const int tid = threadIdx.x, lane = tid & 31, wid = tid >> 5;
    const int qt = blockIdx.x, bhid = blockIdx.y;
    const int b = bhid >> 4, h = bhid & 15;
    const size_t base = ((size_t)(b * SEQ) * HEADS + h) * DHEAD;
    const uint4* Qhp = reinterpret_cast<const uint4*>(Qh + base);
    const uint4* Qlp = reinterpret_cast<const uint4*>(Ql + base);
    const uint4* Khp = reinterpret_cast<const uint4*>(Kh + base);
    const uint4* Klp = reinterpret_cast<const uint4*>(Kl + base);
    const uint4* Vhp = reinterpret_cast<const uint4*>(Vh + base);

    const int lrw = tid >> 3, lcl = tid & 7;

    auto load_kv = [&](int jt, int s) {
        const uint32_t kvb = sb + FA_KV0 + s * FA_KVS;
#pragma unroll
        for (int r4 = 0; r4 < 2; r4++) {
            int row = lrw + r4 * 32;
            uint32_t off = SWZ128(row * 128 + lcl * 16);
            int g = (jt * 64 + row) * 128 + lcl;
            cp16(kvb + off, Khp + g);
            cp16(kvb + FA_KL_O + off, Klp + g);
            cp16(kvb + FA_VH_O + off, Vhp + g);
        }
        CP_COMMIT();
    };

    load_kv(0, 0);
#pragma unroll
    for (int r4 = 0; r4 < 4; r4++) {
        int row = lrw + r4 * 32;
        uint32_t off = SWZ128(row * 128 + lcl * 16);
        int g = (qt * 128 + row) * 128 + lcl;
        *reinterpret_cast<uint4*>(smem + off) = Qhp[g];
        *reinterpret_cast<uint4*>(smem + FA_QL + off) = Qlp[g];
    }

    float m0 = -1e30f, m1 = -1e30f, l0 = 0.f, l1 = 0.f;
    float o[8][4] = {};
    const int fr = lane >> 2, fc = (lane & 3) * 2;
    const int qrow = wid * 16;
    const int aRow = lane & 15, aCol = (lane >> 4) * 16;       // Q A-frag
    const int kRow = ((lane >> 4) & 1) * 8 + (lane & 7);       // K B-frag x4
    const int kHalf = ((lane >> 3) & 1) * 16;
    const int vRow = lane & 15;                                 // V B-frag x4t
    const int vColOff = ((lane >> 4) & 1) * 8;

    CP_WAIT0();
    __syncthreads();

    for (int jt = 0; jt < SEQ / 64; jt++) {
        const uint32_t kvb = sb + FA_KV0 + (jt & 1) * FA_KVS;
        if (jt + 1 < SEQ / 64) load_kv(jt + 1, (jt + 1) & 1);

        // ---- S = Q K^T (fp16 x3), term-major in jj-pairs ----
        float s[8][4] = {};
#pragma unroll
        for (int ks = 0; ks < 4; ks++) {
            uint32_t ah[4], al[4];
            uint32_t offA = SWZ128((qrow + aRow) * 128 + ks * 32 + aCol);
            ldsm_x4(ah, sb + offA);
            ldsm_x4(al, sb + FA_QL + offA);
#pragma unroll
            for (int jp = 0; jp < 2; jp++) {
                uint32_t kh4[2][4], kl4[2][4];
#pragma unroll
                for (int u = 0; u < 2; u++) {
                    int jj = jp * 2 + u;
                    uint32_t offB = SWZ128((jj * 16 + kRow) * 128 + ks * 32 + kHalf);
                    ldsm_x4(kh4[u], kvb + offB);
                    ldsm_x4(kl4[u], kvb + FA_KL_O + offB);
                }
#pragma unroll
                for (int u = 0; u < 2; u++) {
                    int jj = jp * 2 + u;
                    mma_f16(s[2 * jj], ah, kh4[u]);
                    mma_f16(s[2 * jj + 1], ah, kh4[u] + 2);
                }
#pragma unroll
                for (int u = 0; u < 2; u++) {
                    int jj = jp * 2 + u;
                    mma_f16(s[2 * jj], ah, kl4[u]);
                    mma_f16(s[2 * jj + 1], ah, kl4[u] + 2);
                }
#pragma unroll
                for (int u = 0; u < 2; u++) {
                    int jj = jp * 2 + u;
                    mma_f16(s[2 * jj], al, kh4[u]);
                    mma_f16(s[2 * jj + 1], al, kh4[u] + 2);
                }
            }
        }

        // ---- warp-local row max ----
        float rm0 = s[0][0], rm1 = s[0][2];
#pragma unroll
        for (int j = 0; j < 8; j++) {
            rm0 = fmaxf(rm0, fmaxf(s[j][0], s[j][1]));
            rm1 = fmaxf(rm1, fmaxf(s[j][2], s[j][3]));
        }
        rm0 = fmaxf(rm0, __shfl_xor_sync(0xffffffffu, rm0, 1));
        rm0 = fmaxf(rm0, __shfl_xor_sync(0xffffffffu, rm0, 2));
        rm1 = fmaxf(rm1, __shfl_xor_sync(0xffffffffu, rm1, 1));
        rm1 = fmaxf(rm1, __shfl_xor_sync(0xffffffffu, rm1, 2));
        float mn0 = fmaxf(m0, rm0), mn1 = fmaxf(m1, rm1);
        float a0 = __expf(m0 - mn0), a1 = __expf(m1 - mn1);
        m0 = mn0; m1 = mn1;

        // rescale O
#pragma unroll
        for (int j = 0; j < 8; j++) {
            o[j][0] *= a0; o[j][1] *= a0;
            o[j][2] *= a1; o[j][3] *= a1;
        }

        // ---- PV x1 (plain fp16 P and V), exp fused into loop ----
        float rs0 = 0.f, rs1 = 0.f;
#pragma unroll
        for (int kt = 0; kt < 4; kt++) {
            uint32_t pA[4];
#pragma unroll
            for (int u = 0; u < 2; u++) {
                int j = 2 * kt + u;
                float p0 = __expf(s[j][0] - mn0);
                float p1 = __expf(s[j][1] - mn0);
                float p2 = __expf(s[j][2] - mn1);
                float p3 = __expf(s[j][3] - mn1);
                rs0 += p0 + p1; rs1 += p2 + p3;
                __half2 t01 = __floats2half2_rn(p0, p1);
                __half2 t23 = __floats2half2_rn(p2, p3);
                pA[2 * u] = *reinterpret_cast<uint32_t*>(&t01);
                pA[2 * u + 1] = *reinterpret_cast<uint32_t*>(&t23);
            }
#pragma unroll
            for (int jj = 0; jj < 4; jj++) {
                uint32_t vh4[4];
                uint32_t offV = SWZ128((kt * 16 + vRow) * 128 + (jj * 16 + vColOff) * 2);
                ldsm_x4t(vh4, kvb + FA_VH_O + offV);
                mma_f16(o[2 * jj], pA, vh4);
                mma_f16(o[2 * jj + 1], pA, vh4 + 2);
            }
        }
        rs0 += __shfl_xor_sync(0xffffffffu, rs0, 1);
        rs0 += __shfl_xor_sync(0xffffffffu, rs0, 2);
        rs1 += __shfl_xor_sync(0xffffffffu, rs1, 1);
        rs1 += __shfl_xor_sync(0xffffffffu, rs1, 2);
        l0 = l0 * a0 + rs0;
        l1 = l1 * a1 + rs1;

        if (jt + 1 < SEQ / 64) CP_WAIT0();
        __syncthreads();
    }

    // ---- epilogue: normalize, split, store [b,n,h,e] ----
    float inv0 = 1.f / l0, inv1 = 1.f / l1;
    const int r0g = qt * 128 + qrow + fr;
#pragma unroll
    for (int j = 0; j < 8; j++) {
        int col = j * 8 + fc;
        uint32_t h01, l01;
        hsplit2(o[j][0] * inv0, o[j][1] * inv0, h01, l01);
        *reinterpret_cast<uint32_t*>(Oh + base + (size_t)r0g * 1024 + col) = h01;
        *reinterpret_cast<uint32_t*>(Ol + base + (size_t)r0g * 1024 + col) = l01;
        hsplit2(o[j][2] * inv1, o[j][3] * inv1, h01, l01);
        *reinterpret_cast<uint32_t*>(Oh + base + (size_t)(r0g + 8) * 1024 + col) = h01;
        *reinterpret_cast<uint32_t*>(Ol + base + (size_t)(r0g + 8) * 1024 + col) = l01;
    }
}

// ---------------- launch ------------------------------------------------------
extern "C" void kernel_launch(void* const* d_in, const int* in_sizes, int n_in,
                              void* d_out, int out_size) {
    const float* tokens = (const float*)d_in[0];
    const float* wq = (const float*)d_in[1];
    const float* wk = (const float*)d_in[2];
    const float* wv = (const float*)d_in[3];
    const float* wo = (const float*)d_in[4];
    float* out = (float*)d_out;

    __half *tokh, *tokl, *qh, *ql, *kh, *kl, *vh, *vl, *aggh, *aggl;
    __half *wqh, *wql, *wkh, *wkl, *wvh, *wvl, *woh, *wol;
    cudaGetSymbolAddress((void**)&tokh, g_tokh);
    cudaGetSymbolAddress((void**)&tokl, g_tokl);
    cudaGetSymbolAddress((void**)&qh, g_qh);
    cudaGetSymbolAddress((void**)&ql, g_ql);
    cudaGetSymbolAddress((void**)&kh, g_kh);
    cudaGetSymbolAddress((void**)&kl, g_kl);
    cudaGetSymbolAddress((void**)&vh, g_vh);
    cudaGetSymbolAddress((void**)&vl, g_vl);
    cudaGetSymbolAddress((void**)&aggh, g_aggh);
    cudaGetSymbolAddress((void**)&aggl, g_aggl);
    cudaGetSymbolAddress((void**)&wqh, g_wqh);
    cudaGetSymbolAddress((void**)&wql, g_wql);
    cudaGetSymbolAddress((void**)&wkh, g_wkh);
    cudaGetSymbolAddress((void**)&wkl, g_wkl);
    cudaGetSymbolAddress((void**)&wvh, g_wvh);
    cudaGetSymbolAddress((void**)&wvl, g_wvl);
    cudaGetSymbolAddress((void**)&woh, g_woh);
    cudaGetSymbolAddress((void**)&wol, g_wol);

    split_act<<<(BS * DIM / 4 + 255) / 256, 256>>>(
        (const float4*)tokens, tokh, tokl, BS * DIM / 4);
    pack_w<<<(DIM * DIM + 255) / 256, 256>>>(wq, wk, wv, wo);

    cudaFuncSetAttribute(gemm_qkv, cudaFuncAttributeMaxDynamicSharedMemorySize,
                         GS2_TOTAL);
    cudaFuncSetAttribute(gemm_wo, cudaFuncAttributeMaxDynamicSharedMemorySize,
                         GS2_TOTAL);

    QKVArgs args;
    args.bh[0] = wqh; args.bl[0] = wql; args.ch[0] = qh; args.cl[0] = ql;
    args.bh[1] = wkh; args.bl[1] = wkl; args.ch[1] = kh; args.cl[1] = kl;
    args.bh[2] = wvh; args.bl[2] = wvl; args.ch[2] = vh; args.cl[2] = vl;

    dim3 gqkv(DIM / 64, BS / 128, 3);
    gemm_qkv<<<gqkv, 256, GS2_TOTAL>>>(tokh, tokl, args);

    cudaFuncSetAttribute(flash_attn_mma,
                         cudaFuncAttributeMaxDynamicSharedMemorySize, FA_TOTAL);
    flash_attn_mma<<<dim3(SEQ / 128, BATCH * HEADS), 256, FA_TOTAL>>>(
        qh, ql, kh, kl, vh, aggh, aggl);

    dim3 gp(DIM / 64, BS / 128);
    gemm_wo<<<gp, 256, GS2_TOTAL>>>(aggh, aggl, woh, wol, out);
}